// round 2
// baseline (speedup 1.0000x reference)
#include <cuda_runtime.h>

#define C 256            // IN_C == OUT_C == 256
#define MAX_NODES 50048  // padded capacity for scratch
#define MAX_CLUSTERS 128 // assign values are 0..99

// Scratch (allocation-free rule: __device__ globals)
__device__ float g_xW[(size_t)MAX_NODES * C];
__device__ float g_deg[MAX_NODES];
__device__ int   g_cedge[MAX_CLUSTERS];

// ---------------------------------------------------------------------------
// Kernel 1: init deg = 1 (self loop), cluster edge flags = 0
// ---------------------------------------------------------------------------
__global__ void init_kernel(int n_nodes) {
    int i = blockIdx.x * blockDim.x + threadIdx.x;
    if (i < n_nodes) g_deg[i] = 1.0f;
    if (i < MAX_CLUSTERS) g_cedge[i] = 0;
}

// ---------------------------------------------------------------------------
// Kernel 2: degree + has_edge from intra-cluster edges
// ---------------------------------------------------------------------------
__global__ void edge_deg_kernel(const int* __restrict__ src,
                                const int* __restrict__ dst,
                                const int* __restrict__ assign,
                                int n_edges) {
    int e = blockIdx.x * blockDim.x + threadIdx.x;
    if (e >= n_edges) return;
    int s = src[e], d = dst[e];
    int a = assign[s];
    if (a == assign[d]) {
        atomicAdd(&g_deg[d], 1.0f);
        g_cedge[a] = 1;  // idempotent racy store of 1 — fine
    }
}

// ---------------------------------------------------------------------------
// Kernel 3: xW = X @ W (fp32, 64x64x32 smem tiling, 256 threads, 4x4/thread).
// Epilogue: g_xW = raw; out = raw / deg[row] + b[col]  (self-loop + bias).
// ---------------------------------------------------------------------------
__global__ __launch_bounds__(256) void gemm_kernel(
    const float* __restrict__ X, const float* __restrict__ W,
    const float* __restrict__ b, float* __restrict__ out, int M) {
    __shared__ float As[32][65];  // transposed A tile: As[k][m], padded
    __shared__ float Bs[32][64];  // Bs[k][n]

    const int bm = blockIdx.x * 64;
    const int bn = blockIdx.y * 64;
    const int tid = threadIdx.x;
    const int tr = tid >> 4;   // 0..15, row group
    const int tc = tid & 15;   // 0..15, col group

    float acc[4][4] = {};

    // A-tile load mapping: 512 float4 per tile, 2 per thread
    // idx -> row = idx/8, kc = (idx%8)*4
    // B-tile load mapping: idx -> row = idx/16, nc = (idx%16)*4
    for (int kt = 0; kt < C; kt += 32) {
        #pragma unroll
        for (int p = 0; p < 2; p++) {
            int idx = tid + p * 256;
            // A
            int ar = idx >> 3;
            int akc = (idx & 7) * 4;
            float4 av = make_float4(0.f, 0.f, 0.f, 0.f);
            int grow = bm + ar;
            if (grow < M)
                av = *(const float4*)(X + (size_t)grow * C + kt + akc);
            As[akc + 0][ar] = av.x;
            As[akc + 1][ar] = av.y;
            As[akc + 2][ar] = av.z;
            As[akc + 3][ar] = av.w;
            // B
            int br = idx >> 4;
            int bnc = (idx & 15) * 4;
            float4 bv = *(const float4*)(W + (size_t)(kt + br) * C + bn + bnc);
            *(float4*)&Bs[br][bnc] = bv;
        }
        __syncthreads();

        #pragma unroll
        for (int k = 0; k < 32; k++) {
            float a0 = As[k][tr * 4 + 0];
            float a1 = As[k][tr * 4 + 1];
            float a2 = As[k][tr * 4 + 2];
            float a3 = As[k][tr * 4 + 3];
            float4 bv = *(float4*)&Bs[k][tc * 4];
            acc[0][0] += a0 * bv.x; acc[0][1] += a0 * bv.y; acc[0][2] += a0 * bv.z; acc[0][3] += a0 * bv.w;
            acc[1][0] += a1 * bv.x; acc[1][1] += a1 * bv.y; acc[1][2] += a1 * bv.z; acc[1][3] += a1 * bv.w;
            acc[2][0] += a2 * bv.x; acc[2][1] += a2 * bv.y; acc[2][2] += a2 * bv.z; acc[2][3] += a2 * bv.w;
            acc[3][0] += a3 * bv.x; acc[3][1] += a3 * bv.y; acc[3][2] += a3 * bv.z; acc[3][3] += a3 * bv.w;
        }
        __syncthreads();
    }

    // epilogue
    float4 bb = *(const float4*)(b + bn + tc * 4);
    #pragma unroll
    for (int i = 0; i < 4; i++) {
        int row = bm + tr * 4 + i;
        if (row >= M) continue;
        float inv = 1.0f / g_deg[row];
        float4 raw = make_float4(acc[i][0], acc[i][1], acc[i][2], acc[i][3]);
        *(float4*)(g_xW + (size_t)row * C + bn + tc * 4) = raw;
        float4 o;
        o.x = raw.x * inv + bb.x;
        o.y = raw.y * inv + bb.y;
        o.z = raw.z * inv + bb.z;
        o.w = raw.w * inv + bb.w;
        *(float4*)(out + (size_t)row * C + bn + tc * 4) = o;
    }
}

// ---------------------------------------------------------------------------
// Kernel 4: edge scatter. One warp per edge; vector RED into out[dst].
// ---------------------------------------------------------------------------
__device__ __forceinline__ void red_add4(float* addr, float4 v) {
    asm volatile("red.global.add.v4.f32 [%0], {%1, %2, %3, %4};"
                 :: "l"(addr), "f"(v.x), "f"(v.y), "f"(v.z), "f"(v.w)
                 : "memory");
}

__global__ __launch_bounds__(256) void scatter_kernel(
    const int* __restrict__ src, const int* __restrict__ dst,
    const int* __restrict__ assign, float* __restrict__ out, int n_edges) {
    int gwarp = (blockIdx.x * blockDim.x + threadIdx.x) >> 5;
    int lane = threadIdx.x & 31;
    if (gwarp >= n_edges) return;
    int s = src[gwarp], d = dst[gwarp];
    if (assign[s] != assign[d]) return;
    float w = rsqrtf(g_deg[s]) * rsqrtf(g_deg[d]);

    const float4* xs = (const float4*)(g_xW + (size_t)s * C);
    float* od = out + (size_t)d * C;

    float4 v0 = xs[lane];          // floats [lane*4 .. lane*4+3]
    v0.x *= w; v0.y *= w; v0.z *= w; v0.w *= w;
    red_add4(od + lane * 4, v0);

    float4 v1 = xs[lane + 32];     // floats [128 + lane*4 ..]
    v1.x *= w; v1.y *= w; v1.z *= w; v1.w *= w;
    red_add4(od + 128 + lane * 4, v1);
}

// ---------------------------------------------------------------------------
// Kernel 5: restore X for nodes in clusters with zero intra edges
// ---------------------------------------------------------------------------
__global__ void finalize_kernel(const float* __restrict__ X,
                                const int* __restrict__ assign,
                                float* __restrict__ out, int n_nodes) {
    int i = blockIdx.x * blockDim.x + threadIdx.x;  // float4 granularity
    int node = i >> 6;  // 64 float4 per node
    if (node >= n_nodes) return;
    if (g_cedge[assign[node]] == 0) {
        ((float4*)out)[i] = ((const float4*)X)[i];
    }
}

// ---------------------------------------------------------------------------
extern "C" void kernel_launch(void* const* d_in, const int* in_sizes, int n_in,
                              void* d_out, int out_size) {
    const float* X      = (const float*)d_in[0];
    const float* W      = (const float*)d_in[1];
    const float* b      = (const float*)d_in[2];
    const int*   assign = (const int*)d_in[3];
    const int*   ei     = (const int*)d_in[4];

    int n_nodes = in_sizes[0] / C;
    int n_edges = in_sizes[4] / 2;
    const int* src = ei;
    const int* dst = ei + n_edges;
    float* out = (float*)d_out;

    init_kernel<<<(n_nodes + 255) / 256, 256>>>(n_nodes);
    edge_deg_kernel<<<(n_edges + 255) / 256, 256>>>(src, dst, assign, n_edges);

    dim3 ggrid((n_nodes + 63) / 64, C / 64);
    gemm_kernel<<<ggrid, 256>>>(X, W, b, out, n_nodes);

    int scatter_threads = n_edges * 32;
    scatter_kernel<<<(scatter_threads + 255) / 256, 256>>>(src, dst, assign, out, n_edges);

    int fin_threads = n_nodes * (C / 4);
    finalize_kernel<<<(fin_threads + 255) / 256, 256>>>(X, assign, out, n_nodes);
}

// round 4
// speedup vs baseline: 1.7443x; 1.7443x over previous
#include <cuda_runtime.h>
#include <cstdint>

#define C 256            // IN_C == OUT_C == 256
#define MAX_NODES 50048
#define MAX_CLUSTERS 128

// ---- GEMM tiling ----
#define BM 128           // CTA tile M (nodes)
#define BN 128           // CTA tile N (out channels)
#define BK 32            // K per stage
#define NSTAGE (C / BK)  // 8
#define A_STRIDE 36      // floats per A smem row  (36 % 32 == 4 -> conflict-free frag gather)
#define B_STRIDE 136     // floats per B smem row  (136 % 32 == 8 -> conflict-free frag gather)
#define A_BYTES (BM * A_STRIDE * 4)          // 18432
#define B_BYTES (BK * B_STRIDE * 4)          // 17408
#define STAGE_BYTES (A_BYTES + B_BYTES)      // 35840
#define SMEM_TOTAL (2 * STAGE_BYTES)         // 71680

// Scratch (allocation-free rule: __device__ globals)
__device__ float g_xW[(size_t)MAX_NODES * C];
__device__ float g_deg[MAX_NODES];
__device__ int   g_cedge[MAX_CLUSTERS];

// ---------------------------------------------------------------------------
// helpers
// ---------------------------------------------------------------------------
__device__ __forceinline__ uint32_t smem_u32(const void* p) {
    uint32_t a;
    asm("{ .reg .u64 t; cvta.to.shared.u64 t, %1; cvt.u32.u64 %0, t; }"
        : "=r"(a) : "l"(p));
    return a;
}
__device__ __forceinline__ uint32_t f2tf32(float x) {
    uint32_t r;
    asm("cvt.rna.tf32.f32 %0, %1;" : "=r"(r) : "f"(x));
    return r;
}
__device__ __forceinline__ void cp_async16(uint32_t dst, const void* src, int szbytes) {
    asm volatile("cp.async.cg.shared.global [%0], [%1], 16, %2;"
                 :: "r"(dst), "l"(src), "r"(szbytes) : "memory");
}
#define CP_COMMIT() asm volatile("cp.async.commit_group;" ::: "memory")
#define CP_WAIT(n)  asm volatile("cp.async.wait_group %0;" :: "n"(n) : "memory")

__device__ __forceinline__ void mma_tf32(float& d0, float& d1, float& d2, float& d3,
                                         uint32_t a0, uint32_t a1, uint32_t a2, uint32_t a3,
                                         uint32_t b0, uint32_t b1) {
    asm volatile(
        "mma.sync.aligned.m16n8k8.row.col.f32.tf32.tf32.f32 "
        "{%0,%1,%2,%3}, {%4,%5,%6,%7}, {%8,%9}, {%0,%1,%2,%3};"
        : "+f"(d0), "+f"(d1), "+f"(d2), "+f"(d3)
        : "r"(a0), "r"(a1), "r"(a2), "r"(a3), "r"(b0), "r"(b1));
}

// ---------------------------------------------------------------------------
// Kernel 1: init deg = 1 (self loop), cluster edge flags = 0
// ---------------------------------------------------------------------------
__global__ void init_kernel(int n_nodes) {
    int i = blockIdx.x * blockDim.x + threadIdx.x;
    if (i < n_nodes) g_deg[i] = 1.0f;
    if (i < MAX_CLUSTERS) g_cedge[i] = 0;
}

// ---------------------------------------------------------------------------
// Kernel 2: degree + has_edge from intra-cluster edges
// ---------------------------------------------------------------------------
__global__ void edge_deg_kernel(const int* __restrict__ src,
                                const int* __restrict__ dst,
                                const int* __restrict__ assign,
                                int n_edges) {
    int e = blockIdx.x * blockDim.x + threadIdx.x;
    if (e >= n_edges) return;
    int s = src[e], d = dst[e];
    int a = assign[s];
    if (a == assign[d]) {
        atomicAdd(&g_deg[d], 1.0f);
        g_cedge[a] = 1;
    }
}

// ---------------------------------------------------------------------------
// Kernel 3: tf32 mma.sync GEMM, out = X @ W.
// CTA 128x128, 8 warps (2x4), warp tile 64x32 (m16n8k8 frags 4x4),
// K staged 32 deep with cp.async double buffering.
// Epilogue: g_xW = raw; out = raw/deg[row] + b[col].
// ---------------------------------------------------------------------------
__global__ __launch_bounds__(256, 2) void gemm_tc_kernel(
    const float* __restrict__ X, const float* __restrict__ W,
    const float* __restrict__ b, float* __restrict__ out, int n_nodes) {
    extern __shared__ float smem[];

    const int tid = threadIdx.x;
    const int wid = tid >> 5;
    const int lane = tid & 31;
    const int g = lane >> 2;      // groupID 0..7
    const int t = lane & 3;       // thread-in-group 0..3
    const int wm = wid >> 2;      // 0..1  (M warp)
    const int wn = wid & 3;       // 0..3  (N warp)

    const int mbase = blockIdx.x * BM;
    const int nbase = blockIdx.y * BN;

    const uint32_t sbase = smem_u32(smem);

    float acc[4][4][4];
    #pragma unroll
    for (int i = 0; i < 4; i++)
        #pragma unroll
        for (int j = 0; j < 4; j++)
            #pragma unroll
            for (int k = 0; k < 4; k++) acc[i][j][k] = 0.f;

    // ---- stage loader: A tile [BM x BK] from X, B tile [BK x BN] from W ----
    auto load_stage = [&](int ks, int buf) {
        const int kofs = ks * BK;
        const uint32_t sA = sbase + buf * STAGE_BYTES;
        const uint32_t sB = sA + A_BYTES;
        // A: 128 rows x 32 floats = 1024 x 16B
        #pragma unroll
        for (int p = 0; p < 4; p++) {
            int i = tid + p * 256;
            int m = i >> 3, seg = i & 7;
            int node = mbase + m;
            int ok = node < n_nodes;
            const float* src = X + (size_t)(ok ? node : 0) * C + kofs + seg * 4;
            cp_async16(sA + (uint32_t)(m * A_STRIDE + seg * 4) * 4, src, ok ? 16 : 0);
        }
        // B: 32 rows x 128 floats = 1024 x 16B
        #pragma unroll
        for (int p = 0; p < 4; p++) {
            int i = tid + p * 256;
            int k = i >> 5, seg = i & 31;
            const float* src = W + (size_t)(kofs + k) * C + nbase + seg * 4;
            cp_async16(sB + (uint32_t)(k * B_STRIDE + seg * 4) * 4, src, 16);
        }
    };

    load_stage(0, 0);
    CP_COMMIT();

    for (int ks = 0; ks < NSTAGE; ks++) {
        if (ks < NSTAGE - 1) {
            load_stage(ks + 1, (ks + 1) & 1);
            CP_COMMIT();
            CP_WAIT(1);
        } else {
            CP_WAIT(0);
        }
        __syncthreads();

        const float* As = smem + (ks & 1) * (STAGE_BYTES / 4);
        const float* Bs = As + (A_BYTES / 4);

        #pragma unroll
        for (int kk = 0; kk < BK; kk += 8) {
            uint32_t af[4][4], bf[4][2];
            #pragma unroll
            for (int mi = 0; mi < 4; mi++) {
                int r = wm * 64 + mi * 16 + g;
                af[mi][0] = f2tf32(As[r * A_STRIDE + kk + t]);
                af[mi][1] = f2tf32(As[(r + 8) * A_STRIDE + kk + t]);
                af[mi][2] = f2tf32(As[r * A_STRIDE + kk + t + 4]);
                af[mi][3] = f2tf32(As[(r + 8) * A_STRIDE + kk + t + 4]);
            }
            #pragma unroll
            for (int ni = 0; ni < 4; ni++) {
                int cn = wn * 32 + ni * 8 + g;
                bf[ni][0] = f2tf32(Bs[(kk + t) * B_STRIDE + cn]);
                bf[ni][1] = f2tf32(Bs[(kk + t + 4) * B_STRIDE + cn]);
            }
            #pragma unroll
            for (int mi = 0; mi < 4; mi++)
                #pragma unroll
                for (int ni = 0; ni < 4; ni++)
                    mma_tf32(acc[mi][ni][0], acc[mi][ni][1], acc[mi][ni][2], acc[mi][ni][3],
                             af[mi][0], af[mi][1], af[mi][2], af[mi][3],
                             bf[ni][0], bf[ni][1]);
        }
        __syncthreads();
    }

    // ---- epilogue: D frag (mi,ni): c0/c1 at (row g, col 2t..2t+1), c2/c3 at row g+8
    #pragma unroll
    for (int mi = 0; mi < 4; mi++) {
        int r0 = mbase + wm * 64 + mi * 16 + g;
        int r1 = r0 + 8;
        float inv0 = (r0 < n_nodes) ? 1.0f / g_deg[r0] : 0.f;
        float inv1 = (r1 < n_nodes) ? 1.0f / g_deg[r1] : 0.f;
        #pragma unroll
        for (int ni = 0; ni < 4; ni++) {
            int col = nbase + wn * 32 + ni * 8 + t * 2;
            float bx = b[col], by = b[col + 1];
            if (r0 < n_nodes) {
                float v0 = acc[mi][ni][0], v1 = acc[mi][ni][1];
                *(float2*)(g_xW + (size_t)r0 * C + col) = make_float2(v0, v1);
                *(float2*)(out + (size_t)r0 * C + col) =
                    make_float2(v0 * inv0 + bx, v1 * inv0 + by);
            }
            if (r1 < n_nodes) {
                float v2 = acc[mi][ni][2], v3 = acc[mi][ni][3];
                *(float2*)(g_xW + (size_t)r1 * C + col) = make_float2(v2, v3);
                *(float2*)(out + (size_t)r1 * C + col) =
                    make_float2(v2 * inv1 + bx, v3 * inv1 + by);
            }
        }
    }
}

// ---------------------------------------------------------------------------
// Kernel 4: edge scatter. One warp per edge; vector RED into out[dst].
// ---------------------------------------------------------------------------
__device__ __forceinline__ void red_add4(float* addr, float4 v) {
    asm volatile("red.global.add.v4.f32 [%0], {%1, %2, %3, %4};"
                 :: "l"(addr), "f"(v.x), "f"(v.y), "f"(v.z), "f"(v.w)
                 : "memory");
}

__global__ __launch_bounds__(256) void scatter_kernel(
    const int* __restrict__ src, const int* __restrict__ dst,
    const int* __restrict__ assign, float* __restrict__ out, int n_edges) {
    int gwarp = (blockIdx.x * blockDim.x + threadIdx.x) >> 5;
    int lane = threadIdx.x & 31;
    if (gwarp >= n_edges) return;
    int s = src[gwarp], d = dst[gwarp];
    if (assign[s] != assign[d]) return;
    float w = rsqrtf(g_deg[s]) * rsqrtf(g_deg[d]);

    const float4* xs = (const float4*)(g_xW + (size_t)s * C);
    float* od = out + (size_t)d * C;

    float4 v0 = xs[lane];
    v0.x *= w; v0.y *= w; v0.z *= w; v0.w *= w;
    red_add4(od + lane * 4, v0);

    float4 v1 = xs[lane + 32];
    v1.x *= w; v1.y *= w; v1.z *= w; v1.w *= w;
    red_add4(od + 128 + lane * 4, v1);
}

// ---------------------------------------------------------------------------
// Kernel 5: restore X for nodes in clusters with zero intra edges
// ---------------------------------------------------------------------------
__global__ void finalize_kernel(const float* __restrict__ X,
                                const int* __restrict__ assign,
                                float* __restrict__ out, int n_nodes) {
    int i = blockIdx.x * blockDim.x + threadIdx.x;  // float4 granularity
    int node = i >> 6;
    if (node >= n_nodes) return;
    if (g_cedge[assign[node]] == 0) {
        ((float4*)out)[i] = ((const float4*)X)[i];
    }
}

// ---------------------------------------------------------------------------
extern "C" void kernel_launch(void* const* d_in, const int* in_sizes, int n_in,
                              void* d_out, int out_size) {
    const float* X      = (const float*)d_in[0];
    const float* W      = (const float*)d_in[1];
    const float* b      = (const float*)d_in[2];
    const int*   assign = (const int*)d_in[3];
    const int*   ei     = (const int*)d_in[4];

    int n_nodes = in_sizes[0] / C;
    int n_edges = in_sizes[4] / 2;
    const int* src = ei;
    const int* dst = ei + n_edges;
    float* out = (float*)d_out;

    cudaFuncSetAttribute(gemm_tc_kernel,
                         cudaFuncAttributeMaxDynamicSharedMemorySize, SMEM_TOTAL);

    init_kernel<<<(n_nodes + 255) / 256, 256>>>(n_nodes);
    edge_deg_kernel<<<(n_edges + 255) / 256, 256>>>(src, dst, assign, n_edges);

    dim3 ggrid((n_nodes + BM - 1) / BM, C / BN);
    gemm_tc_kernel<<<ggrid, 256, SMEM_TOTAL>>>(X, W, b, out, n_nodes);

    int scatter_threads = n_edges * 32;
    scatter_kernel<<<(scatter_threads + 255) / 256, 256>>>(src, dst, assign, out, n_edges);

    int fin_threads = n_nodes * (C / 4);
    finalize_kernel<<<(fin_threads + 255) / 256, 256>>>(X, assign, out, n_nodes);
}

// round 6
// speedup vs baseline: 2.3810x; 1.3650x over previous
#include <cuda_runtime.h>
#include <cstdint>

#define C 256            // IN_C == OUT_C == 256
#define MAX_NODES 50048
#define MAX_CLUSTERS 128
#define CAP 64           // max in-degree bucket (Poisson(5.4) -> max ~25)

// ---- GEMM tiling ----
#define BM 128           // CTA tile M (nodes)
#define BN 128           // CTA tile N (out channels)
#define BK 32            // K per stage
#define NSTAGE (C / BK)  // 8
#define A_STRIDE 36      // floats per A smem row  (36 % 32 == 4 -> conflict-free frag gather)
#define B_STRIDE 136     // floats per B smem row  (136 % 32 == 8 -> conflict-free frag gather)
#define A_BYTES (BM * A_STRIDE * 4)          // 18432
#define B_BYTES (BK * B_STRIDE * 4)          // 17408
#define STAGE_BYTES (A_BYTES + B_BYTES)      // 35840
#define SMEM_TOTAL (2 * STAGE_BYTES)         // 71680

// Scratch (allocation-free rule: __device__ globals)
__device__ float g_xWs[(size_t)MAX_NODES * C];   // xW * rsqrt(deg), per row
__device__ int   g_cnt[MAX_NODES];               // intra in-degree
__device__ int   g_adj[(size_t)MAX_NODES * CAP]; // per-dst src buckets
__device__ int   g_cedge[MAX_CLUSTERS];

// ---------------------------------------------------------------------------
// helpers
// ---------------------------------------------------------------------------
__device__ __forceinline__ uint32_t f2tf32(float x) {
    uint32_t r;
    asm("cvt.rna.tf32.f32 %0, %1;" : "=r"(r) : "f"(x));
    return r;
}
__device__ __forceinline__ uint32_t smem_u32(const void* p) {
    uint32_t a;
    asm("{ .reg .u64 t; cvta.to.shared.u64 t, %1; cvt.u32.u64 %0, t; }"
        : "=r"(a) : "l"(p));
    return a;
}
__device__ __forceinline__ void cp_async16(uint32_t dst, const void* src, int szbytes) {
    asm volatile("cp.async.cg.shared.global [%0], [%1], 16, %2;"
                 :: "r"(dst), "l"(src), "r"(szbytes) : "memory");
}
#define CP_COMMIT() asm volatile("cp.async.commit_group;" ::: "memory")
#define CP_WAIT(n)  asm volatile("cp.async.wait_group %0;" :: "n"(n) : "memory")

__device__ __forceinline__ void mma_tf32(float& d0, float& d1, float& d2, float& d3,
                                         uint32_t a0, uint32_t a1, uint32_t a2, uint32_t a3,
                                         uint32_t b0, uint32_t b1) {
    asm volatile(
        "mma.sync.aligned.m16n8k8.row.col.f32.tf32.tf32.f32 "
        "{%0,%1,%2,%3}, {%4,%5,%6,%7}, {%8,%9}, {%0,%1,%2,%3};"
        : "+f"(d0), "+f"(d1), "+f"(d2), "+f"(d3)
        : "r"(a0), "r"(a1), "r"(a2), "r"(a3), "r"(b0), "r"(b1));
}

// ---------------------------------------------------------------------------
// Kernel 1: init counts + cluster flags
// ---------------------------------------------------------------------------
__global__ void init_kernel(int n_nodes) {
    int i = blockIdx.x * blockDim.x + threadIdx.x;
    if (i < n_nodes) g_cnt[i] = 0;
    if (i < MAX_CLUSTERS) g_cedge[i] = 0;
}

// ---------------------------------------------------------------------------
// Kernel 2: build per-dst adjacency buckets for intra-cluster edges.
// atomicAdd returns the bucket slot -> no scan needed.
// ---------------------------------------------------------------------------
__global__ void edge_build_kernel(const int* __restrict__ src,
                                  const int* __restrict__ dst,
                                  const int* __restrict__ assign,
                                  int n_edges) {
    int e = blockIdx.x * blockDim.x + threadIdx.x;
    if (e >= n_edges) return;
    int s = src[e], d = dst[e];
    int a = assign[s];
    if (a == assign[d]) {
        int pos = atomicAdd(&g_cnt[d], 1);
        if (pos < CAP) g_adj[(size_t)d * CAP + pos] = s;
        g_cedge[a] = 1;
    }
}

// ---------------------------------------------------------------------------
// Kernel 3: tf32 mma.sync GEMM.  g_xWs[row] = (X@W)[row] * rsqrt(deg[row]).
// CTA 128x128, 8 warps (2x4), warp tile 64x32, cp.async double buffering.
// ---------------------------------------------------------------------------
__global__ __launch_bounds__(256, 2) void gemm_tc_kernel(
    const float* __restrict__ X, const float* __restrict__ W, int n_nodes) {
    extern __shared__ float smem[];

    const int tid = threadIdx.x;
    const int wid = tid >> 5;
    const int lane = tid & 31;
    const int g = lane >> 2;      // groupID 0..7
    const int t = lane & 3;       // thread-in-group 0..3
    const int wm = wid >> 2;      // 0..1  (M warp)
    const int wn = wid & 3;       // 0..3  (N warp)

    const int mbase = blockIdx.x * BM;
    const int nbase = blockIdx.y * BN;

    const uint32_t sbase = smem_u32(smem);

    float acc[4][4][4];
    #pragma unroll
    for (int i = 0; i < 4; i++)
        #pragma unroll
        for (int j = 0; j < 4; j++)
            #pragma unroll
            for (int k = 0; k < 4; k++) acc[i][j][k] = 0.f;

    auto load_stage = [&](int ks, int buf) {
        const int kofs = ks * BK;
        const uint32_t sA = sbase + buf * STAGE_BYTES;
        const uint32_t sB = sA + A_BYTES;
        #pragma unroll
        for (int p = 0; p < 4; p++) {
            int i = tid + p * 256;
            int m = i >> 3, seg = i & 7;
            int node = mbase + m;
            int ok = node < n_nodes;
            const float* src = X + (size_t)(ok ? node : 0) * C + kofs + seg * 4;
            cp_async16(sA + (uint32_t)(m * A_STRIDE + seg * 4) * 4, src, ok ? 16 : 0);
        }
        #pragma unroll
        for (int p = 0; p < 4; p++) {
            int i = tid + p * 256;
            int k = i >> 5, seg = i & 31;
            const float* src = W + (size_t)(kofs + k) * C + nbase + seg * 4;
            cp_async16(sB + (uint32_t)(k * B_STRIDE + seg * 4) * 4, src, 16);
        }
    };

    load_stage(0, 0);
    CP_COMMIT();

    for (int ks = 0; ks < NSTAGE; ks++) {
        if (ks < NSTAGE - 1) {
            load_stage(ks + 1, (ks + 1) & 1);
            CP_COMMIT();
            CP_WAIT(1);
        } else {
            CP_WAIT(0);
        }
        __syncthreads();

        const float* As = smem + (ks & 1) * (STAGE_BYTES / 4);
        const float* Bs = As + (A_BYTES / 4);

        #pragma unroll
        for (int kk = 0; kk < BK; kk += 8) {
            uint32_t af[4][4], bf[4][2];
            #pragma unroll
            for (int mi = 0; mi < 4; mi++) {
                int r = wm * 64 + mi * 16 + g;
                af[mi][0] = f2tf32(As[r * A_STRIDE + kk + t]);
                af[mi][1] = f2tf32(As[(r + 8) * A_STRIDE + kk + t]);
                af[mi][2] = f2tf32(As[r * A_STRIDE + kk + t + 4]);
                af[mi][3] = f2tf32(As[(r + 8) * A_STRIDE + kk + t + 4]);
            }
            #pragma unroll
            for (int ni = 0; ni < 4; ni++) {
                int cn = wn * 32 + ni * 8 + g;
                bf[ni][0] = f2tf32(Bs[(kk + t) * B_STRIDE + cn]);
                bf[ni][1] = f2tf32(Bs[(kk + t + 4) * B_STRIDE + cn]);
            }
            #pragma unroll
            for (int mi = 0; mi < 4; mi++)
                #pragma unroll
                for (int ni = 0; ni < 4; ni++)
                    mma_tf32(acc[mi][ni][0], acc[mi][ni][1], acc[mi][ni][2], acc[mi][ni][3],
                             af[mi][0], af[mi][1], af[mi][2], af[mi][3],
                             bf[ni][0], bf[ni][1]);
        }
        __syncthreads();
    }

    // epilogue: g_xWs[row] = raw * rsqrt(1 + cnt[row])
    #pragma unroll
    for (int mi = 0; mi < 4; mi++) {
        int r0 = mbase + wm * 64 + mi * 16 + g;
        int r1 = r0 + 8;
        float dis0 = (r0 < n_nodes) ? rsqrtf(1.0f + (float)g_cnt[r0]) : 0.f;
        float dis1 = (r1 < n_nodes) ? rsqrtf(1.0f + (float)g_cnt[r1]) : 0.f;
        #pragma unroll
        for (int ni = 0; ni < 4; ni++) {
            int col = nbase + wn * 32 + ni * 8 + t * 2;
            if (r0 < n_nodes)
                *(float2*)(g_xWs + (size_t)r0 * C + col) =
                    make_float2(acc[mi][ni][0] * dis0, acc[mi][ni][1] * dis0);
            if (r1 < n_nodes)
                *(float2*)(g_xWs + (size_t)r1 * C + col) =
                    make_float2(acc[mi][ni][2] * dis1, acc[mi][ni][3] * dis1);
        }
    }
}

// ---------------------------------------------------------------------------
// Kernel 4: atomic-free gather. One warp per dst node.
// out[d] = dis[d] * (g_xWs[d] + sum_{src in adj[d]} g_xWs[src]) + b
// (self term has weight 1 because xW[d]/deg = g_xWs[d]*dis[d])
// Nodes in edgeless clusters copy X through unchanged.
// ---------------------------------------------------------------------------
__global__ __launch_bounds__(256) void gather_kernel(
    const float* __restrict__ X, const float* __restrict__ b,
    const int* __restrict__ assign, float* __restrict__ out, int n_nodes) {
    int node = (blockIdx.x * blockDim.x + threadIdx.x) >> 5;
    int lane = threadIdx.x & 31;
    if (node >= n_nodes) return;

    float4* orow = (float4*)(out + (size_t)node * C);

    if (g_cedge[assign[node]] == 0) {
        const float4* xrow = (const float4*)(X + (size_t)node * C);
        orow[lane] = xrow[lane];
        orow[lane + 32] = xrow[lane + 32];
        return;
    }

    int cnt = g_cnt[node];
    float dis = rsqrtf(1.0f + (float)cnt);

    const float4* self = (const float4*)(g_xWs + (size_t)node * C);
    float4 a0 = self[lane];
    float4 a1 = self[lane + 32];

    const int* adj = g_adj + (size_t)node * CAP;
    int e = 0;
    for (; e + 2 <= cnt; e += 2) {
        int s0 = adj[e], s1 = adj[e + 1];
        const float4* x0 = (const float4*)(g_xWs + (size_t)s0 * C);
        const float4* x1 = (const float4*)(g_xWs + (size_t)s1 * C);
        float4 v00 = x0[lane],      v01 = x0[lane + 32];
        float4 v10 = x1[lane],      v11 = x1[lane + 32];
        a0.x += v00.x + v10.x; a0.y += v00.y + v10.y;
        a0.z += v00.z + v10.z; a0.w += v00.w + v10.w;
        a1.x += v01.x + v11.x; a1.y += v01.y + v11.y;
        a1.z += v01.z + v11.z; a1.w += v01.w + v11.w;
    }
    if (e < cnt) {
        int s0 = adj[e];
        const float4* x0 = (const float4*)(g_xWs + (size_t)s0 * C);
        float4 v00 = x0[lane], v01 = x0[lane + 32];
        a0.x += v00.x; a0.y += v00.y; a0.z += v00.z; a0.w += v00.w;
        a1.x += v01.x; a1.y += v01.y; a1.z += v01.z; a1.w += v01.w;
    }

    const float4* brow = (const float4*)b;
    float4 b0 = brow[lane], b1 = brow[lane + 32];
    float4 o0, o1;
    o0.x = a0.x * dis + b0.x; o0.y = a0.y * dis + b0.y;
    o0.z = a0.z * dis + b0.z; o0.w = a0.w * dis + b0.w;
    o1.x = a1.x * dis + b1.x; o1.y = a1.y * dis + b1.y;
    o1.z = a1.z * dis + b1.z; o1.w = a1.w * dis + b1.w;
    orow[lane] = o0;
    orow[lane + 32] = o1;
}

// ---------------------------------------------------------------------------
extern "C" void kernel_launch(void* const* d_in, const int* in_sizes, int n_in,
                              void* d_out, int out_size) {
    const float* X      = (const float*)d_in[0];
    const float* W      = (const float*)d_in[1];
    const float* b      = (const float*)d_in[2];
    const int*   assign = (const int*)d_in[3];
    const int*   ei     = (const int*)d_in[4];

    int n_nodes = in_sizes[0] / C;
    int n_edges = in_sizes[4] / 2;
    const int* src = ei;
    const int* dst = ei + n_edges;
    float* out = (float*)d_out;

    cudaFuncSetAttribute(gemm_tc_kernel,
                         cudaFuncAttributeMaxDynamicSharedMemorySize, SMEM_TOTAL);

    init_kernel<<<(n_nodes + 255) / 256, 256>>>(n_nodes);
    edge_build_kernel<<<(n_edges + 255) / 256, 256>>>(src, dst, assign, n_edges);

    dim3 ggrid((n_nodes + BM - 1) / BM, C / BN);
    gemm_tc_kernel<<<ggrid, 256, SMEM_TOTAL>>>(X, W, n_nodes);

    int gth = n_nodes * 32;
    gather_kernel<<<(gth + 255) / 256, 256>>>(X, b, assign, out, n_nodes);
}

// round 9
// speedup vs baseline: 2.5760x; 1.0819x over previous
#include <cuda_runtime.h>
#include <cuda_fp16.h>
#include <cstdint>

#define C 256            // IN_C == OUT_C == 256
#define MAX_NODES 50048
#define MAX_CLUSTERS 128
#define CAP 64           // max in-degree bucket (Poisson(5.4) -> max ~25)

// ---- GEMM tiling (fp16 m16n8k16) ----
#define BM 128           // CTA tile M (nodes)
#define BN 128           // CTA tile N (out channels)
#define BKH 64           // K halves per stage (64*2B = 128B rows)
#define NSTAGE (C / BKH) // 4
#define ROW_BYTES 144    // padded row: 9 x 16B (odd) -> conflict-free ldmatrix
#define A_BYTES (BM * ROW_BYTES)             // 18432
#define B_BYTES (BN * ROW_BYTES)             // 18432 (B stored n-major)
#define STAGE_BYTES (A_BYTES + B_BYTES)      // 36864
#define SMEM_TOTAL (2 * STAGE_BYTES)         // 73728

// Scratch (allocation-free rule: __device__ globals)
__device__ float  g_xWs[(size_t)MAX_NODES * C];   // xW * rsqrt(deg), per row
__device__ __half g_Xh[(size_t)MAX_NODES * C];    // X in fp16
__device__ __half g_WhT[C * C];                   // W^T in fp16: [oc][ic]
__device__ int    g_cnt[MAX_NODES];               // intra in-degree
__device__ int    g_adj[(size_t)MAX_NODES * CAP]; // per-dst src buckets
__device__ int    g_cedge[MAX_CLUSTERS];

// ---------------------------------------------------------------------------
// helpers
// ---------------------------------------------------------------------------
__device__ __forceinline__ uint32_t smem_u32(const void* p) {
    uint32_t a;
    asm("{ .reg .u64 t; cvta.to.shared.u64 t, %1; cvt.u32.u64 %0, t; }"
        : "=r"(a) : "l"(p));
    return a;
}
__device__ __forceinline__ void cp_async16(uint32_t dst, const void* src, int szbytes) {
    asm volatile("cp.async.cg.shared.global [%0], [%1], 16, %2;"
                 :: "r"(dst), "l"(src), "r"(szbytes) : "memory");
}
#define CP_COMMIT() asm volatile("cp.async.commit_group;" ::: "memory")
#define CP_WAIT(n)  asm volatile("cp.async.wait_group %0;" :: "n"(n) : "memory")

__device__ __forceinline__ void ldsm_x4(uint32_t& r0, uint32_t& r1,
                                        uint32_t& r2, uint32_t& r3, uint32_t addr) {
    asm volatile("ldmatrix.sync.aligned.m8n8.x4.shared.b16 {%0,%1,%2,%3}, [%4];"
                 : "=r"(r0), "=r"(r1), "=r"(r2), "=r"(r3) : "r"(addr));
}

__device__ __forceinline__ void mma_f16(float& d0, float& d1, float& d2, float& d3,
                                        uint32_t a0, uint32_t a1, uint32_t a2, uint32_t a3,
                                        uint32_t b0, uint32_t b1) {
    asm volatile(
        "mma.sync.aligned.m16n8k16.row.col.f32.f16.f16.f32 "
        "{%0,%1,%2,%3}, {%4,%5,%6,%7}, {%8,%9}, {%0,%1,%2,%3};"
        : "+f"(d0), "+f"(d1), "+f"(d2), "+f"(d3)
        : "r"(a0), "r"(a1), "r"(a2), "r"(a3), "r"(b0), "r"(b1));
}

// ---------------------------------------------------------------------------
// Kernel 1: init counts + cluster flags
// ---------------------------------------------------------------------------
__global__ void init_kernel(int n_nodes) {
    int i = blockIdx.x * blockDim.x + threadIdx.x;
    if (i < n_nodes) g_cnt[i] = 0;
    if (i < MAX_CLUSTERS) g_cedge[i] = 0;
}

// ---------------------------------------------------------------------------
// Kernel 2: build per-dst adjacency buckets for intra-cluster edges.
// ---------------------------------------------------------------------------
__global__ void edge_build_kernel(const int* __restrict__ src,
                                  const int* __restrict__ dst,
                                  const int* __restrict__ assign,
                                  int n_edges) {
    int e = blockIdx.x * blockDim.x + threadIdx.x;
    if (e >= n_edges) return;
    int s = src[e], d = dst[e];
    int a = assign[s];
    if (a == assign[d]) {
        int pos = atomicAdd(&g_cnt[d], 1);
        if (pos < CAP) g_adj[(size_t)d * CAP + pos] = s;
        g_cedge[a] = 1;
    }
}

// ---------------------------------------------------------------------------
// Kernel 2b: convert X -> fp16 (8 halves = 16B per thread)
// ---------------------------------------------------------------------------
__global__ void xconv_kernel(const float* __restrict__ X, int total8) {
    int i = blockIdx.x * blockDim.x + threadIdx.x;
    if (i >= total8) return;
    const float4* src = (const float4*)X + i * 2;
    float4 v0 = src[0], v1 = src[1];
    __half2 h[4];
    h[0] = __floats2half2_rn(v0.x, v0.y);
    h[1] = __floats2half2_rn(v0.z, v0.w);
    h[2] = __floats2half2_rn(v1.x, v1.y);
    h[3] = __floats2half2_rn(v1.z, v1.w);
    *(uint4*)(g_Xh + (size_t)i * 8) = *(uint4*)h;
}

// ---------------------------------------------------------------------------
// Kernel 2c: W -> fp16 transposed: g_WhT[oc][ic] = half(W[ic][oc])
// ---------------------------------------------------------------------------
__global__ void wconv_kernel(const float* __restrict__ W) {
    __shared__ float t[32][33];
    int bx = blockIdx.x * 32;   // oc tile
    int by = blockIdx.y * 32;   // ic tile
    for (int j = threadIdx.y; j < 32; j += 8)
        t[j][threadIdx.x] = W[(size_t)(by + j) * C + bx + threadIdx.x];
    __syncthreads();
    for (int j = threadIdx.y; j < 32; j += 8)
        g_WhT[(size_t)(bx + j) * C + by + threadIdx.x] = __float2half_rn(t[threadIdx.x][j]);
}

// ---------------------------------------------------------------------------
// Kernel 3: fp16 mma.sync GEMM. g_xWs[row] = (X@W)[row] * rsqrt(deg[row]).
// CTA 128x128, 8 warps (2x4), warp tile 64x32 (m16n8k16 frags 4x4),
// A = g_Xh [m][k], B = g_WhT [n][k]; both K-contiguous -> plain ldmatrix.
// K staged 64 deep, cp.async double buffering.
// ---------------------------------------------------------------------------
__global__ __launch_bounds__(256, 2) void gemm_tc_kernel(int n_nodes) {
    extern __shared__ char smem[];

    const int tid = threadIdx.x;
    const int wid = tid >> 5;
    const int lane = tid & 31;
    const int g = lane >> 2;      // groupID 0..7
    const int t = lane & 3;       // thread-in-group 0..3
    const int wm = wid >> 2;      // 0..1  (M warp)
    const int wn = wid & 3;       // 0..3  (N warp)

    const int mbase = blockIdx.x * BM;
    const int nbase = blockIdx.y * BN;

    const uint32_t sbase = smem_u32(smem);

    // ldmatrix per-lane addressing offsets
    const int a_row = lane & 15;            // + (lane>>4)*16B column
    const int a_byte = (lane >> 4) * 16;
    const int b_row = (lane & 7) + ((lane >> 4) * 8);
    const int b_byte = ((lane >> 3) & 1) * 16;

    float acc[4][4][4];
    #pragma unroll
    for (int i = 0; i < 4; i++)
        #pragma unroll
        for (int j = 0; j < 4; j++)
            #pragma unroll
            for (int k = 0; k < 4; k++) acc[i][j][k] = 0.f;

    // stage tile: A 128 rows x 8 chunks of 16B, B 128 n-rows x 8 chunks.
    // 1024 chunks each side, 256 threads -> 4 chunks/thread/side.
    auto load_stage = [&](int ks, int buf) {
        const int kofs = ks * BKH;   // halves
        const uint32_t sA = sbase + buf * STAGE_BYTES;
        const uint32_t sB = sA + A_BYTES;
        #pragma unroll
        for (int p = 0; p < 4; p++) {
            int i = tid + p * 256;
            int m = i >> 3, seg = i & 7;
            int node = mbase + m;
            int ok = node < n_nodes;
            const __half* src = g_Xh + (size_t)(ok ? node : 0) * C + kofs + seg * 8;
            cp_async16(sA + (uint32_t)(m * ROW_BYTES + seg * 16), src, ok ? 16 : 0);
        }
        #pragma unroll
        for (int p = 0; p < 4; p++) {
            int i = tid + p * 256;
            int n = i >> 3, seg = i & 7;
            const __half* src = g_WhT + (size_t)(nbase + n) * C + kofs + seg * 8;
            cp_async16(sB + (uint32_t)(n * ROW_BYTES + seg * 16), src, 16);
        }
    };

    load_stage(0, 0);
    CP_COMMIT();

    for (int ks = 0; ks < NSTAGE; ks++) {
        if (ks < NSTAGE - 1) {
            load_stage(ks + 1, (ks + 1) & 1);
            CP_COMMIT();
            CP_WAIT(1);
        } else {
            CP_WAIT(0);
        }
        __syncthreads();

        const uint32_t sA = sbase + (ks & 1) * STAGE_BYTES;
        const uint32_t sB = sA + A_BYTES;

        #pragma unroll
        for (int kk = 0; kk < BKH; kk += 16) {
            uint32_t af[4][4], bf[2][4];
            #pragma unroll
            for (int mi = 0; mi < 4; mi++) {
                int r = wm * 64 + mi * 16 + a_row;
                ldsm_x4(af[mi][0], af[mi][1], af[mi][2], af[mi][3],
                        sA + (uint32_t)(r * ROW_BYTES + kk * 2 + a_byte));
            }
            #pragma unroll
            for (int ni2 = 0; ni2 < 2; ni2++) {
                int n = wn * 32 + ni2 * 16 + b_row;
                ldsm_x4(bf[ni2][0], bf[ni2][1], bf[ni2][2], bf[ni2][3],
                        sB + (uint32_t)(n * ROW_BYTES + kk * 2 + b_byte));
            }
            #pragma unroll
            for (int mi = 0; mi < 4; mi++)
                #pragma unroll
                for (int ni = 0; ni < 4; ni++)
                    mma_f16(acc[mi][ni][0], acc[mi][ni][1], acc[mi][ni][2], acc[mi][ni][3],
                            af[mi][0], af[mi][1], af[mi][2], af[mi][3],
                            bf[ni >> 1][(ni & 1) * 2], bf[ni >> 1][(ni & 1) * 2 + 1]);
        }
        __syncthreads();
    }

    // epilogue: g_xWs[row] = raw * rsqrt(1 + cnt[row])
    #pragma unroll
    for (int mi = 0; mi < 4; mi++) {
        int r0 = mbase + wm * 64 + mi * 16 + g;
        int r1 = r0 + 8;
        float dis0 = (r0 < n_nodes) ? rsqrtf(1.0f + (float)g_cnt[r0]) : 0.f;
        float dis1 = (r1 < n_nodes) ? rsqrtf(1.0f + (float)g_cnt[r1]) : 0.f;
        #pragma unroll
        for (int ni = 0; ni < 4; ni++) {
            int col = nbase + wn * 32 + ni * 8 + t * 2;
            if (r0 < n_nodes)
                *(float2*)(g_xWs + (size_t)r0 * C + col) =
                    make_float2(acc[mi][ni][0] * dis0, acc[mi][ni][1] * dis0);
            if (r1 < n_nodes)
                *(float2*)(g_xWs + (size_t)r1 * C + col) =
                    make_float2(acc[mi][ni][2] * dis1, acc[mi][ni][3] * dis1);
        }
    }
}

// ---------------------------------------------------------------------------
// Kernel 4: atomic-free gather. One warp per dst node.
// out[d] = dis[d] * (g_xWs[d] + sum_{src in adj[d]} g_xWs[src]) + b
// ---------------------------------------------------------------------------
__global__ __launch_bounds__(256) void gather_kernel(
    const float* __restrict__ X, const float* __restrict__ b,
    const int* __restrict__ assign, float* __restrict__ out, int n_nodes) {
    int node = (blockIdx.x * blockDim.x + threadIdx.x) >> 5;
    int lane = threadIdx.x & 31;
    if (node >= n_nodes) return;

    float4* orow = (float4*)(out + (size_t)node * C);

    if (g_cedge[assign[node]] == 0) {
        const float4* xrow = (const float4*)(X + (size_t)node * C);
        orow[lane] = xrow[lane];
        orow[lane + 32] = xrow[lane + 32];
        return;
    }

    int cnt = g_cnt[node];
    float dis = rsqrtf(1.0f + (float)cnt);

    const float4* self = (const float4*)(g_xWs + (size_t)node * C);
    float4 a0 = self[lane];
    float4 a1 = self[lane + 32];

    const int* adj = g_adj + (size_t)node * CAP;
    int e = 0;
    for (; e + 2 <= cnt; e += 2) {
        int s0 = adj[e], s1 = adj[e + 1];
        const float4* x0 = (const float4*)(g_xWs + (size_t)s0 * C);
        const float4* x1 = (const float4*)(g_xWs + (size_t)s1 * C);
        float4 v00 = x0[lane],      v01 = x0[lane + 32];
        float4 v10 = x1[lane],      v11 = x1[lane + 32];
        a0.x += v00.x + v10.x; a0.y += v00.y + v10.y;
        a0.z += v00.z + v10.z; a0.w += v00.w + v10.w;
        a1.x += v01.x + v11.x; a1.y += v01.y + v11.y;
        a1.z += v01.z + v11.z; a1.w += v01.w + v11.w;
    }
    if (e < cnt) {
        int s0 = adj[e];
        const float4* x0 = (const float4*)(g_xWs + (size_t)s0 * C);
        float4 v00 = x0[lane], v01 = x0[lane + 32];
        a0.x += v00.x; a0.y += v00.y; a0.z += v00.z; a0.w += v00.w;
        a1.x += v01.x; a1.y += v01.y; a1.z += v01.z; a1.w += v01.w;
    }

    const float4* brow = (const float4*)b;
    float4 b0 = brow[lane], b1 = brow[lane + 32];
    float4 o0, o1;
    o0.x = a0.x * dis + b0.x; o0.y = a0.y * dis + b0.y;
    o0.z = a0.z * dis + b0.z; o0.w = a0.w * dis + b0.w;
    o1.x = a1.x * dis + b1.x; o1.y = a1.y * dis + b1.y;
    o1.z = a1.z * dis + b1.z; o1.w = a1.w * dis + b1.w;
    orow[lane] = o0;
    orow[lane + 32] = o1;
}

// ---------------------------------------------------------------------------
extern "C" void kernel_launch(void* const* d_in, const int* in_sizes, int n_in,
                              void* d_out, int out_size) {
    const float* X      = (const float*)d_in[0];
    const float* W      = (const float*)d_in[1];
    const float* b      = (const float*)d_in[2];
    const int*   assign = (const int*)d_in[3];
    const int*   ei     = (const int*)d_in[4];

    int n_nodes = in_sizes[0] / C;
    int n_edges = in_sizes[4] / 2;
    const int* src = ei;
    const int* dst = ei + n_edges;
    float* out = (float*)d_out;

    cudaFuncSetAttribute(gemm_tc_kernel,
                         cudaFuncAttributeMaxDynamicSharedMemorySize, SMEM_TOTAL);

    init_kernel<<<(n_nodes + 255) / 256, 256>>>(n_nodes);
    edge_build_kernel<<<(n_edges + 255) / 256, 256>>>(src, dst, assign, n_edges);

    int total8 = (n_nodes * C) / 8;
    xconv_kernel<<<(total8 + 255) / 256, 256>>>(X, total8);
    wconv_kernel<<<dim3(C / 32, C / 32), dim3(32, 8)>>>(W);

    dim3 ggrid((n_nodes + BM - 1) / BM, C / BN);
    gemm_tc_kernel<<<ggrid, 256, SMEM_TOTAL>>>(n_nodes);

    int gth = n_nodes * 32;
    gather_kernel<<<(gth + 255) / 256, 256>>>(X, b, assign, out, n_nodes);
}

// round 10
// speedup vs baseline: 2.5977x; 1.0084x over previous
#include <cuda_runtime.h>
#include <cuda_fp16.h>
#include <cstdint>

#define C 256            // IN_C == OUT_C == 256
#define MAX_NODES 50048
#define MAX_CLUSTERS 128
#define CAP 64           // max in-degree bucket (Poisson(5.4) -> max ~25)

// ---- GEMM tiling (fp16 m16n8k16) ----
#define BM 128           // CTA tile M (nodes)
#define BN 128           // CTA tile N (out channels)
#define BKH 64           // K halves per stage (64*2B = 128B rows)
#define NSTAGE (C / BKH) // 4
#define ROW_BYTES 144    // padded row: 9 x 16B (odd) -> conflict-free ldmatrix
#define A_BYTES (BM * ROW_BYTES)             // 18432
#define B_BYTES (BN * ROW_BYTES)             // 18432 (B stored n-major)
#define STAGE_BYTES (A_BYTES + B_BYTES)      // 36864
#define SMEM_TOTAL (2 * STAGE_BYTES)         // 73728

// Scratch (allocation-free rule: __device__ globals)
__device__ float  g_xWs[(size_t)MAX_NODES * C];   // xW * rsqrt(deg), per row
__device__ __half g_WhT[C * C];                   // W^T in fp16: [oc][ic]
__device__ int    g_cnt[MAX_NODES];               // intra in-degree
__device__ int    g_adj[(size_t)MAX_NODES * CAP]; // per-dst src buckets
__device__ int    g_cedge[MAX_CLUSTERS];

// ---------------------------------------------------------------------------
// helpers
// ---------------------------------------------------------------------------
__device__ __forceinline__ uint32_t smem_u32(const void* p) {
    uint32_t a;
    asm("{ .reg .u64 t; cvta.to.shared.u64 t, %1; cvt.u32.u64 %0, t; }"
        : "=r"(a) : "l"(p));
    return a;
}
__device__ __forceinline__ void cp_async16(uint32_t dst, const void* src) {
    asm volatile("cp.async.cg.shared.global [%0], [%1], 16;"
                 :: "r"(dst), "l"(src) : "memory");
}
#define CP_COMMIT() asm volatile("cp.async.commit_group;" ::: "memory")
#define CP_WAIT(n)  asm volatile("cp.async.wait_group %0;" :: "n"(n) : "memory")

__device__ __forceinline__ void ldsm_x4(uint32_t& r0, uint32_t& r1,
                                        uint32_t& r2, uint32_t& r3, uint32_t addr) {
    asm volatile("ldmatrix.sync.aligned.m8n8.x4.shared.b16 {%0,%1,%2,%3}, [%4];"
                 : "=r"(r0), "=r"(r1), "=r"(r2), "=r"(r3) : "r"(addr));
}

__device__ __forceinline__ void mma_f16(float& d0, float& d1, float& d2, float& d3,
                                        uint32_t a0, uint32_t a1, uint32_t a2, uint32_t a3,
                                        uint32_t b0, uint32_t b1) {
    asm volatile(
        "mma.sync.aligned.m16n8k16.row.col.f32.f16.f16.f32 "
        "{%0,%1,%2,%3}, {%4,%5,%6,%7}, {%8,%9}, {%0,%1,%2,%3};"
        : "+f"(d0), "+f"(d1), "+f"(d2), "+f"(d3)
        : "r"(a0), "r"(a1), "r"(a2), "r"(a3), "r"(b0), "r"(b1));
}

__device__ __forceinline__ uint4 pack8h(float4 v0, float4 v1) {
    __half2 h[4];
    h[0] = __floats2half2_rn(v0.x, v0.y);
    h[1] = __floats2half2_rn(v0.z, v0.w);
    h[2] = __floats2half2_rn(v1.x, v1.y);
    h[3] = __floats2half2_rn(v1.z, v1.w);
    return *(uint4*)h;
}

// ---------------------------------------------------------------------------
// Kernel 1: init counts + cluster flags  AND  W -> fp16 transposed.
// Blocks [0, NB_INIT): init.  Blocks [NB_INIT, NB_INIT+64): wconv tiles.
// ---------------------------------------------------------------------------
#define NB_INIT 196
__global__ void init_wconv_kernel(const float* __restrict__ W, int n_nodes) {
    __shared__ float t[32][33];
    int blk = blockIdx.x;
    if (blk < NB_INIT) {
        int i = blk * 256 + threadIdx.x;
        if (i < n_nodes) g_cnt[i] = 0;
        if (i < MAX_CLUSTERS) g_cedge[i] = 0;
        return;
    }
    int wb = blk - NB_INIT;            // 0..63 -> 8x8 tiles of 32x32
    int bx = (wb & 7) * 32;            // oc tile
    int by = (wb >> 3) * 32;           // ic tile
    int tx = threadIdx.x & 31;
    int ty = threadIdx.x >> 5;         // 0..7
    for (int j = ty; j < 32; j += 8)
        t[j][tx] = W[(size_t)(by + j) * C + bx + tx];
    __syncthreads();
    for (int j = ty; j < 32; j += 8)
        g_WhT[(size_t)(bx + j) * C + by + tx] = __float2half_rn(t[tx][j]);
}

// ---------------------------------------------------------------------------
// Kernel 2: build per-dst adjacency buckets for intra-cluster edges.
// ---------------------------------------------------------------------------
__global__ void edge_build_kernel(const int* __restrict__ src,
                                  const int* __restrict__ dst,
                                  const int* __restrict__ assign,
                                  int n_edges) {
    int e = blockIdx.x * blockDim.x + threadIdx.x;
    if (e >= n_edges) return;
    int s = src[e], d = dst[e];
    int a = assign[s];
    if (a == assign[d]) {
        int pos = atomicAdd(&g_cnt[d], 1);
        if (pos < CAP) g_adj[(size_t)d * CAP + pos] = s;
        g_cedge[a] = 1;
    }
}

// ---------------------------------------------------------------------------
// Kernel 3: fp16 mma.sync GEMM. g_xWs[row] = (X@W)[row] * rsqrt(deg[row]).
// A path reads fp32 X directly (LDG.128 -> cvt -> STS), fused conversion.
// B path cp.async from g_WhT. CTA 128x128, 8 warps, m16n8k16, double buffer.
// ---------------------------------------------------------------------------
__global__ __launch_bounds__(256, 2) void gemm_tc_kernel(
    const float* __restrict__ X, int n_nodes) {
    extern __shared__ char smem[];

    const int tid = threadIdx.x;
    const int wid = tid >> 5;
    const int lane = tid & 31;
    const int g = lane >> 2;
    const int t = lane & 3;
    const int wm = wid >> 2;
    const int wn = wid & 3;

    const int mbase = blockIdx.x * BM;
    const int nbase = blockIdx.y * BN;

    const uint32_t sbase = smem_u32(smem);

    const int a_row = lane & 15;
    const int a_byte = (lane >> 4) * 16;
    const int b_row = (lane & 7) + ((lane >> 4) * 8);
    const int b_byte = ((lane >> 3) & 1) * 16;

    // per-thread A chunk mapping: chunk i in [0,1024): m = i>>3, seg = i&7
    // this thread owns i = tid + p*256, p in 0..3 (batch0: p 0-1, batch1: p 2-3)
    const int am[4]  = { (tid + 0) >> 3, (tid + 256) >> 3, (tid + 512) >> 3, (tid + 768) >> 3 };
    const int aseg[4] = { tid & 7, tid & 7, tid & 7, tid & 7 };  // (i&7) == (tid&7) since 256|p*256

    float acc[4][4][4];
    #pragma unroll
    for (int i = 0; i < 4; i++)
        #pragma unroll
        for (int j = 0; j < 4; j++)
            #pragma unroll
            for (int k = 0; k < 4; k++) acc[i][j][k] = 0.f;

    auto ldg_a2 = [&](int ks, int c, float4& v0, float4& v1) {
        int node = mbase + am[c];
        if (node < n_nodes) {
            const float* src = X + (size_t)node * C + ks * BKH + aseg[c] * 8;
            v0 = *(const float4*)src;
            v1 = *(const float4*)(src + 4);
        } else {
            v0 = make_float4(0.f, 0.f, 0.f, 0.f);
            v1 = v0;
        }
    };
    auto sts_a = [&](int buf, int c, float4 v0, float4 v1) {
        uint32_t dst = sbase + buf * STAGE_BYTES
                     + (uint32_t)(am[c] * ROW_BYTES + aseg[c] * 16);
        *(uint4*)(smem + (dst - sbase)) = pack8h(v0, v1);
    };
    auto cp_b = [&](int ks, int buf) {
        const uint32_t sB = sbase + buf * STAGE_BYTES + A_BYTES;
        #pragma unroll
        for (int p = 0; p < 4; p++) {
            int i = tid + p * 256;
            int n = i >> 3, seg = i & 7;
            const __half* src = g_WhT + (size_t)(nbase + n) * C + ks * BKH + seg * 8;
            cp_async16(sB + (uint32_t)(n * ROW_BYTES + seg * 16), src);
        }
    };

    // prologue: stage 0
    {
        float4 v[8];
        ldg_a2(0, 0, v[0], v[1]); ldg_a2(0, 1, v[2], v[3]);
        ldg_a2(0, 2, v[4], v[5]); ldg_a2(0, 3, v[6], v[7]);
        sts_a(0, 0, v[0], v[1]); sts_a(0, 1, v[2], v[3]);
        sts_a(0, 2, v[4], v[5]); sts_a(0, 3, v[6], v[7]);
        cp_b(0, 0);
        CP_COMMIT();
    }

    for (int ks = 0; ks < NSTAGE; ks++) {
        const int buf = ks & 1;
        const int nbuf = buf ^ 1;
        const bool has_next = (ks < NSTAGE - 1);

        float4 pv[4];
        if (has_next) {
            ldg_a2(ks + 1, 0, pv[0], pv[1]);
            ldg_a2(ks + 1, 1, pv[2], pv[3]);
            cp_b(ks + 1, nbuf);
            CP_COMMIT();
        }
        if (has_next) { CP_WAIT(1); } else { CP_WAIT(0); }
        __syncthreads();

        const uint32_t sA = sbase + buf * STAGE_BYTES;
        const uint32_t sB = sA + A_BYTES;

        // first half of K (kk = 0, 16)
        #pragma unroll
        for (int kk = 0; kk < 32; kk += 16) {
            uint32_t af[4][4], bf[2][4];
            #pragma unroll
            for (int mi = 0; mi < 4; mi++) {
                int r = wm * 64 + mi * 16 + a_row;
                ldsm_x4(af[mi][0], af[mi][1], af[mi][2], af[mi][3],
                        sA + (uint32_t)(r * ROW_BYTES + kk * 2 + a_byte));
            }
            #pragma unroll
            for (int ni2 = 0; ni2 < 2; ni2++) {
                int n = wn * 32 + ni2 * 16 + b_row;
                ldsm_x4(bf[ni2][0], bf[ni2][1], bf[ni2][2], bf[ni2][3],
                        sB + (uint32_t)(n * ROW_BYTES + kk * 2 + b_byte));
            }
            #pragma unroll
            for (int mi = 0; mi < 4; mi++)
                #pragma unroll
                for (int ni = 0; ni < 4; ni++)
                    mma_f16(acc[mi][ni][0], acc[mi][ni][1], acc[mi][ni][2], acc[mi][ni][3],
                            af[mi][0], af[mi][1], af[mi][2], af[mi][3],
                            bf[ni >> 1][(ni & 1) * 2], bf[ni >> 1][(ni & 1) * 2 + 1]);
        }

        if (has_next) {
            sts_a(nbuf, 0, pv[0], pv[1]);
            sts_a(nbuf, 1, pv[2], pv[3]);
            ldg_a2(ks + 1, 2, pv[0], pv[1]);
            ldg_a2(ks + 1, 3, pv[2], pv[3]);
        }

        // second half of K (kk = 32, 48)
        #pragma unroll
        for (int kk = 32; kk < 64; kk += 16) {
            uint32_t af[4][4], bf[2][4];
            #pragma unroll
            for (int mi = 0; mi < 4; mi++) {
                int r = wm * 64 + mi * 16 + a_row;
                ldsm_x4(af[mi][0], af[mi][1], af[mi][2], af[mi][3],
                        sA + (uint32_t)(r * ROW_BYTES + kk * 2 + a_byte));
            }
            #pragma unroll
            for (int ni2 = 0; ni2 < 2; ni2++) {
                int n = wn * 32 + ni2 * 16 + b_row;
                ldsm_x4(bf[ni2][0], bf[ni2][1], bf[ni2][2], bf[ni2][3],
                        sB + (uint32_t)(n * ROW_BYTES + kk * 2 + b_byte));
            }
            #pragma unroll
            for (int mi = 0; mi < 4; mi++)
                #pragma unroll
                for (int ni = 0; ni < 4; ni++)
                    mma_f16(acc[mi][ni][0], acc[mi][ni][1], acc[mi][ni][2], acc[mi][ni][3],
                            af[mi][0], af[mi][1], af[mi][2], af[mi][3],
                            bf[ni >> 1][(ni & 1) * 2], bf[ni >> 1][(ni & 1) * 2 + 1]);
        }

        if (has_next) {
            sts_a(nbuf, 2, pv[0], pv[1]);
            sts_a(nbuf, 3, pv[2], pv[3]);
        }
        __syncthreads();
    }

    // epilogue: g_xWs[row] = raw * rsqrt(1 + cnt[row])
    #pragma unroll
    for (int mi = 0; mi < 4; mi++) {
        int r0 = mbase + wm * 64 + mi * 16 + g;
        int r1 = r0 + 8;
        float dis0 = (r0 < n_nodes) ? rsqrtf(1.0f + (float)g_cnt[r0]) : 0.f;
        float dis1 = (r1 < n_nodes) ? rsqrtf(1.0f + (float)g_cnt[r1]) : 0.f;
        #pragma unroll
        for (int ni = 0; ni < 4; ni++) {
            int col = nbase + wn * 32 + ni * 8 + t * 2;
            if (r0 < n_nodes)
                *(float2*)(g_xWs + (size_t)r0 * C + col) =
                    make_float2(acc[mi][ni][0] * dis0, acc[mi][ni][1] * dis0);
            if (r1 < n_nodes)
                *(float2*)(g_xWs + (size_t)r1 * C + col) =
                    make_float2(acc[mi][ni][2] * dis1, acc[mi][ni][3] * dis1);
        }
    }
}

// ---------------------------------------------------------------------------
// Kernel 4: atomic-free gather. TWO warps per dst node (128 ch each),
// adjacency loop unrolled x4 for MLP.
// out[d] = dis[d] * (g_xWs[d] + sum_{src in adj[d]} g_xWs[src]) + b
// ---------------------------------------------------------------------------
__global__ __launch_bounds__(256) void gather_kernel(
    const float* __restrict__ X, const float* __restrict__ b,
    const int* __restrict__ assign, float* __restrict__ out, int n_nodes) {
    int gwarp = (blockIdx.x * blockDim.x + threadIdx.x) >> 5;
    int node = gwarp >> 1;
    int half = gwarp & 1;
    int lane = threadIdx.x & 31;
    if (node >= n_nodes) return;

    const int coff = half * 32 + lane;           // float4 index within 64-f4 row
    float4* orow = (float4*)(out + (size_t)node * C);

    if (g_cedge[assign[node]] == 0) {
        orow[coff] = ((const float4*)(X + (size_t)node * C))[coff];
        return;
    }

    int cnt = g_cnt[node];
    float dis = rsqrtf(1.0f + (float)cnt);

    const float4* xw = (const float4*)g_xWs;
    float4 a = xw[(size_t)node * 64 + coff];     // self term

    const int* adj = g_adj + (size_t)node * CAP;
    int e = 0;
    for (; e + 4 <= cnt; e += 4) {
        int s0 = adj[e], s1 = adj[e + 1], s2 = adj[e + 2], s3 = adj[e + 3];
        float4 v0 = xw[(size_t)s0 * 64 + coff];
        float4 v1 = xw[(size_t)s1 * 64 + coff];
        float4 v2 = xw[(size_t)s2 * 64 + coff];
        float4 v3 = xw[(size_t)s3 * 64 + coff];
        a.x += (v0.x + v1.x) + (v2.x + v3.x);
        a.y += (v0.y + v1.y) + (v2.y + v3.y);
        a.z += (v0.z + v1.z) + (v2.z + v3.z);
        a.w += (v0.w + v1.w) + (v2.w + v3.w);
    }
    for (; e < cnt; e++) {
        float4 v = xw[(size_t)adj[e] * 64 + coff];
        a.x += v.x; a.y += v.y; a.z += v.z; a.w += v.w;
    }

    float4 bb = ((const float4*)b)[coff];
    orow[coff] = make_float4(a.x * dis + bb.x, a.y * dis + bb.y,
                             a.z * dis + bb.z, a.w * dis + bb.w);
}

// ---------------------------------------------------------------------------
extern "C" void kernel_launch(void* const* d_in, const int* in_sizes, int n_in,
                              void* d_out, int out_size) {
    const float* X      = (const float*)d_in[0];
    const float* W      = (const float*)d_in[1];
    const float* b      = (const float*)d_in[2];
    const int*   assign = (const int*)d_in[3];
    const int*   ei     = (const int*)d_in[4];

    int n_nodes = in_sizes[0] / C;
    int n_edges = in_sizes[4] / 2;
    const int* src = ei;
    const int* dst = ei + n_edges;
    float* out = (float*)d_out;

    cudaFuncSetAttribute(gemm_tc_kernel,
                         cudaFuncAttributeMaxDynamicSharedMemorySize, SMEM_TOTAL);

    init_wconv_kernel<<<NB_INIT + 64, 256>>>(W, n_nodes);
    edge_build_kernel<<<(n_edges + 255) / 256, 256>>>(src, dst, assign, n_edges);

    dim3 ggrid((n_nodes + BM - 1) / BM, C / BN);
    gemm_tc_kernel<<<ggrid, 256, SMEM_TOTAL>>>(X, n_nodes);

    int gth = n_nodes * 64;   // 2 warps per node
    gather_kernel<<<(gth + 255) / 256, 256>>>(X, b, assign, out, n_nodes);
}

// round 11
// speedup vs baseline: 2.8015x; 1.0785x over previous
#include <cuda_runtime.h>
#include <cuda_fp16.h>
#include <cstdint>

#define C 256            // IN_C == OUT_C == 256
#define MAX_NODES 50048
#define MAX_CLUSTERS 128
#define CAP 64           // max in-degree bucket (Poisson(5.4) -> max ~25)

// ---- GEMM tiling (fp16 m16n8k16) ----
#define BM 128           // CTA tile M (nodes)
#define BN 128           // CTA tile N (out channels)
#define BKH 64           // K halves per stage (64*2B = 128B rows)
#define NSTAGE (C / BKH) // 4
#define ROW_BYTES 144    // padded row: 9 x 16B (odd) -> conflict-free ldmatrix
#define A_BYTES (BM * ROW_BYTES)             // 18432
#define B_BYTES (BN * ROW_BYTES)             // 18432 (B stored n-major)
#define STAGE_BYTES (A_BYTES + B_BYTES)      // 36864
#define SMEM_TOTAL (2 * STAGE_BYTES)         // 73728

// Scratch (allocation-free rule: __device__ globals)
__device__ __half g_xWsh[(size_t)MAX_NODES * C]; // xW * rsqrt(deg), fp16
__device__ __half g_WhT[C * C];                  // W^T in fp16: [oc][ic]
__device__ int    g_cnt[MAX_NODES];              // intra in-degree
__device__ int    g_adj[(size_t)MAX_NODES * CAP];// per-dst src buckets
__device__ int    g_cedge[MAX_CLUSTERS];

// ---------------------------------------------------------------------------
// helpers
// ---------------------------------------------------------------------------
__device__ __forceinline__ uint32_t smem_u32(const void* p) {
    uint32_t a;
    asm("{ .reg .u64 t; cvta.to.shared.u64 t, %1; cvt.u32.u64 %0, t; }"
        : "=r"(a) : "l"(p));
    return a;
}
__device__ __forceinline__ void cp_async16(uint32_t dst, const void* src) {
    asm volatile("cp.async.cg.shared.global [%0], [%1], 16;"
                 :: "r"(dst), "l"(src) : "memory");
}
#define CP_COMMIT() asm volatile("cp.async.commit_group;" ::: "memory")
#define CP_WAIT(n)  asm volatile("cp.async.wait_group %0;" :: "n"(n) : "memory")

__device__ __forceinline__ void ldsm_x4(uint32_t& r0, uint32_t& r1,
                                        uint32_t& r2, uint32_t& r3, uint32_t addr) {
    asm volatile("ldmatrix.sync.aligned.m8n8.x4.shared.b16 {%0,%1,%2,%3}, [%4];"
                 : "=r"(r0), "=r"(r1), "=r"(r2), "=r"(r3) : "r"(addr));
}

__device__ __forceinline__ void mma_f16(float& d0, float& d1, float& d2, float& d3,
                                        uint32_t a0, uint32_t a1, uint32_t a2, uint32_t a3,
                                        uint32_t b0, uint32_t b1) {
    asm volatile(
        "mma.sync.aligned.m16n8k16.row.col.f32.f16.f16.f32 "
        "{%0,%1,%2,%3}, {%4,%5,%6,%7}, {%8,%9}, {%0,%1,%2,%3};"
        : "+f"(d0), "+f"(d1), "+f"(d2), "+f"(d3)
        : "r"(a0), "r"(a1), "r"(a2), "r"(a3), "r"(b0), "r"(b1));
}

__device__ __forceinline__ uint4 pack8h(float4 v0, float4 v1) {
    __half2 h[4];
    h[0] = __floats2half2_rn(v0.x, v0.y);
    h[1] = __floats2half2_rn(v0.z, v0.w);
    h[2] = __floats2half2_rn(v1.x, v1.y);
    h[3] = __floats2half2_rn(v1.z, v1.w);
    return *(uint4*)h;
}

// accumulate 4 half2 (a uint4) into 8 fp32 accumulators
__device__ __forceinline__ void acc8(float* a, uint4 v) {
    float2 f0 = __half22float2(*(__half2*)&v.x);
    float2 f1 = __half22float2(*(__half2*)&v.y);
    float2 f2 = __half22float2(*(__half2*)&v.z);
    float2 f3 = __half22float2(*(__half2*)&v.w);
    a[0] += f0.x; a[1] += f0.y; a[2] += f1.x; a[3] += f1.y;
    a[4] += f2.x; a[5] += f2.y; a[6] += f3.x; a[7] += f3.y;
}

// ---------------------------------------------------------------------------
// Kernel 1: init counts + cluster flags  AND  W -> fp16 transposed.
// ---------------------------------------------------------------------------
#define NB_INIT 196
__global__ void init_wconv_kernel(const float* __restrict__ W, int n_nodes) {
    __shared__ float t[32][33];
    int blk = blockIdx.x;
    if (blk < NB_INIT) {
        int i = blk * 256 + threadIdx.x;
        if (i < n_nodes) g_cnt[i] = 0;
        if (i < MAX_CLUSTERS) g_cedge[i] = 0;
        return;
    }
    int wb = blk - NB_INIT;            // 0..63 -> 8x8 tiles of 32x32
    int bx = (wb & 7) * 32;            // oc tile
    int by = (wb >> 3) * 32;           // ic tile
    int tx = threadIdx.x & 31;
    int ty = threadIdx.x >> 5;         // 0..7
    for (int j = ty; j < 32; j += 8)
        t[j][tx] = W[(size_t)(by + j) * C + bx + tx];
    __syncthreads();
    for (int j = ty; j < 32; j += 8)
        g_WhT[(size_t)(bx + j) * C + by + tx] = __float2half_rn(t[tx][j]);
}

// ---------------------------------------------------------------------------
// Kernel 2: build per-dst adjacency buckets for intra-cluster edges.
// ---------------------------------------------------------------------------
__global__ void edge_build_kernel(const int* __restrict__ src,
                                  const int* __restrict__ dst,
                                  const int* __restrict__ assign,
                                  int n_edges) {
    int e = blockIdx.x * blockDim.x + threadIdx.x;
    if (e >= n_edges) return;
    int s = src[e], d = dst[e];
    int a = assign[s];
    if (a == assign[d]) {
        int pos = atomicAdd(&g_cnt[d], 1);
        if (pos < CAP) g_adj[(size_t)d * CAP + pos] = s;
        g_cedge[a] = 1;
    }
}

// ---------------------------------------------------------------------------
// Kernel 3: fp16 mma.sync GEMM. g_xWsh[row] = half((X@W)[row] * rsqrt(deg)).
// A path reads fp32 X directly (LDG.128 -> cvt -> STS), fused conversion.
// B path cp.async from g_WhT. CTA 128x128, 8 warps, m16n8k16, double buffer.
// ---------------------------------------------------------------------------
__global__ __launch_bounds__(256, 2) void gemm_tc_kernel(
    const float* __restrict__ X, int n_nodes) {
    extern __shared__ char smem[];

    const int tid = threadIdx.x;
    const int wid = tid >> 5;
    const int lane = tid & 31;
    const int g = lane >> 2;
    const int t = lane & 3;
    const int wm = wid >> 2;
    const int wn = wid & 3;

    const int mbase = blockIdx.x * BM;
    const int nbase = blockIdx.y * BN;

    const uint32_t sbase = smem_u32(smem);

    const int a_row = lane & 15;
    const int a_byte = (lane >> 4) * 16;
    const int b_row = (lane & 7) + ((lane >> 4) * 8);
    const int b_byte = ((lane >> 3) & 1) * 16;

    const int am[4]  = { (tid + 0) >> 3, (tid + 256) >> 3, (tid + 512) >> 3, (tid + 768) >> 3 };
    const int aseg = tid & 7;

    float acc[4][4][4];
    #pragma unroll
    for (int i = 0; i < 4; i++)
        #pragma unroll
        for (int j = 0; j < 4; j++)
            #pragma unroll
            for (int k = 0; k < 4; k++) acc[i][j][k] = 0.f;

    auto ldg_a2 = [&](int ks, int c, float4& v0, float4& v1) {
        int node = mbase + am[c];
        if (node < n_nodes) {
            const float* src = X + (size_t)node * C + ks * BKH + aseg * 8;
            v0 = *(const float4*)src;
            v1 = *(const float4*)(src + 4);
        } else {
            v0 = make_float4(0.f, 0.f, 0.f, 0.f);
            v1 = v0;
        }
    };
    auto sts_a = [&](int buf, int c, float4 v0, float4 v1) {
        uint32_t off = (uint32_t)(buf * STAGE_BYTES + am[c] * ROW_BYTES + aseg * 16);
        *(uint4*)(smem + off) = pack8h(v0, v1);
    };
    auto cp_b = [&](int ks, int buf) {
        const uint32_t sB = sbase + buf * STAGE_BYTES + A_BYTES;
        #pragma unroll
        for (int p = 0; p < 4; p++) {
            int i = tid + p * 256;
            int n = i >> 3, seg = i & 7;
            const __half* src = g_WhT + (size_t)(nbase + n) * C + ks * BKH + seg * 8;
            cp_async16(sB + (uint32_t)(n * ROW_BYTES + seg * 16), src);
        }
    };

    // prologue: stage 0
    {
        float4 v[8];
        ldg_a2(0, 0, v[0], v[1]); ldg_a2(0, 1, v[2], v[3]);
        ldg_a2(0, 2, v[4], v[5]); ldg_a2(0, 3, v[6], v[7]);
        sts_a(0, 0, v[0], v[1]); sts_a(0, 1, v[2], v[3]);
        sts_a(0, 2, v[4], v[5]); sts_a(0, 3, v[6], v[7]);
        cp_b(0, 0);
        CP_COMMIT();
    }

    for (int ks = 0; ks < NSTAGE; ks++) {
        const int buf = ks & 1;
        const int nbuf = buf ^ 1;
        const bool has_next = (ks < NSTAGE - 1);

        float4 pv[4];
        if (has_next) {
            ldg_a2(ks + 1, 0, pv[0], pv[1]);
            ldg_a2(ks + 1, 1, pv[2], pv[3]);
            cp_b(ks + 1, nbuf);
            CP_COMMIT();
        }
        if (has_next) { CP_WAIT(1); } else { CP_WAIT(0); }
        __syncthreads();

        const uint32_t sA = sbase + buf * STAGE_BYTES;
        const uint32_t sB = sA + A_BYTES;

        #pragma unroll
        for (int kk = 0; kk < 32; kk += 16) {
            uint32_t af[4][4], bf[2][4];
            #pragma unroll
            for (int mi = 0; mi < 4; mi++) {
                int r = wm * 64 + mi * 16 + a_row;
                ldsm_x4(af[mi][0], af[mi][1], af[mi][2], af[mi][3],
                        sA + (uint32_t)(r * ROW_BYTES + kk * 2 + a_byte));
            }
            #pragma unroll
            for (int ni2 = 0; ni2 < 2; ni2++) {
                int n = wn * 32 + ni2 * 16 + b_row;
                ldsm_x4(bf[ni2][0], bf[ni2][1], bf[ni2][2], bf[ni2][3],
                        sB + (uint32_t)(n * ROW_BYTES + kk * 2 + b_byte));
            }
            #pragma unroll
            for (int mi = 0; mi < 4; mi++)
                #pragma unroll
                for (int ni = 0; ni < 4; ni++)
                    mma_f16(acc[mi][ni][0], acc[mi][ni][1], acc[mi][ni][2], acc[mi][ni][3],
                            af[mi][0], af[mi][1], af[mi][2], af[mi][3],
                            bf[ni >> 1][(ni & 1) * 2], bf[ni >> 1][(ni & 1) * 2 + 1]);
        }

        if (has_next) {
            sts_a(nbuf, 0, pv[0], pv[1]);
            sts_a(nbuf, 1, pv[2], pv[3]);
            ldg_a2(ks + 1, 2, pv[0], pv[1]);
            ldg_a2(ks + 1, 3, pv[2], pv[3]);
        }

        #pragma unroll
        for (int kk = 32; kk < 64; kk += 16) {
            uint32_t af[4][4], bf[2][4];
            #pragma unroll
            for (int mi = 0; mi < 4; mi++) {
                int r = wm * 64 + mi * 16 + a_row;
                ldsm_x4(af[mi][0], af[mi][1], af[mi][2], af[mi][3],
                        sA + (uint32_t)(r * ROW_BYTES + kk * 2 + a_byte));
            }
            #pragma unroll
            for (int ni2 = 0; ni2 < 2; ni2++) {
                int n = wn * 32 + ni2 * 16 + b_row;
                ldsm_x4(bf[ni2][0], bf[ni2][1], bf[ni2][2], bf[ni2][3],
                        sB + (uint32_t)(n * ROW_BYTES + kk * 2 + b_byte));
            }
            #pragma unroll
            for (int mi = 0; mi < 4; mi++)
                #pragma unroll
                for (int ni = 0; ni < 4; ni++)
                    mma_f16(acc[mi][ni][0], acc[mi][ni][1], acc[mi][ni][2], acc[mi][ni][3],
                            af[mi][0], af[mi][1], af[mi][2], af[mi][3],
                            bf[ni >> 1][(ni & 1) * 2], bf[ni >> 1][(ni & 1) * 2 + 1]);
        }

        if (has_next) {
            sts_a(nbuf, 2, pv[0], pv[1]);
            sts_a(nbuf, 3, pv[2], pv[3]);
        }
        __syncthreads();
    }

    // epilogue: g_xWsh[row] = half(raw * rsqrt(1 + cnt[row]))
    #pragma unroll
    for (int mi = 0; mi < 4; mi++) {
        int r0 = mbase + wm * 64 + mi * 16 + g;
        int r1 = r0 + 8;
        float dis0 = (r0 < n_nodes) ? rsqrtf(1.0f + (float)g_cnt[r0]) : 0.f;
        float dis1 = (r1 < n_nodes) ? rsqrtf(1.0f + (float)g_cnt[r1]) : 0.f;
        #pragma unroll
        for (int ni = 0; ni < 4; ni++) {
            int col = nbase + wn * 32 + ni * 8 + t * 2;
            if (r0 < n_nodes) {
                __half2 h = __floats2half2_rn(acc[mi][ni][0] * dis0, acc[mi][ni][1] * dis0);
                *(__half2*)(g_xWsh + (size_t)r0 * C + col) = h;
            }
            if (r1 < n_nodes) {
                __half2 h = __floats2half2_rn(acc[mi][ni][2] * dis1, acc[mi][ni][3] * dis1);
                *(__half2*)(g_xWsh + (size_t)r1 * C + col) = h;
            }
        }
    }
}

// ---------------------------------------------------------------------------
// Kernel 4: atomic-free gather over fp16 xWs. One warp per dst node.
// Each lane owns 8 halves (16B) of the 512B row; accumulates in fp32.
// out[d] = dis[d] * (xWs[d] + sum_{src in adj[d]} xWs[src]) + b
// ---------------------------------------------------------------------------
__global__ __launch_bounds__(256) void gather_kernel(
    const float* __restrict__ X, const float* __restrict__ b,
    const int* __restrict__ assign, float* __restrict__ out, int n_nodes) {
    int node = (blockIdx.x * blockDim.x + threadIdx.x) >> 5;
    int lane = threadIdx.x & 31;
    if (node >= n_nodes) return;

    if (g_cedge[assign[node]] == 0) {
        const float4* xrow = (const float4*)(X + (size_t)node * C);
        float4* orow = (float4*)(out + (size_t)node * C);
        orow[lane] = xrow[lane];
        orow[lane + 32] = xrow[lane + 32];
        return;
    }

    int cnt = g_cnt[node];
    if (cnt > CAP) cnt = CAP;
    float dis = rsqrtf(1.0f + (float)cnt);

    const uint4* xw = (const uint4*)g_xWsh;      // 16B = 8 halves per entry
    // row stride in uint4 units: 256 halves / 8 = 32; lane owns entry `lane`
    float a[8] = {0.f, 0.f, 0.f, 0.f, 0.f, 0.f, 0.f, 0.f};
    acc8(a, xw[(size_t)node * 32 + lane]);       // self term

    const int* adj = g_adj + (size_t)node * CAP;
    int e = 0;
    for (; e + 4 <= cnt; e += 4) {
        int s0 = adj[e], s1 = adj[e + 1], s2 = adj[e + 2], s3 = adj[e + 3];
        uint4 v0 = xw[(size_t)s0 * 32 + lane];
        uint4 v1 = xw[(size_t)s1 * 32 + lane];
        uint4 v2 = xw[(size_t)s2 * 32 + lane];
        uint4 v3 = xw[(size_t)s3 * 32 + lane];
        acc8(a, v0); acc8(a, v1); acc8(a, v2); acc8(a, v3);
    }
    for (; e < cnt; e++)
        acc8(a, xw[(size_t)adj[e] * 32 + lane]);

    const float4* brow = (const float4*)b;       // lane owns floats [lane*8, lane*8+8)
    float4 b0 = brow[lane * 2], b1 = brow[lane * 2 + 1];
    float4 o0 = make_float4(a[0] * dis + b0.x, a[1] * dis + b0.y,
                            a[2] * dis + b0.z, a[3] * dis + b0.w);
    float4 o1 = make_float4(a[4] * dis + b1.x, a[5] * dis + b1.y,
                            a[6] * dis + b1.z, a[7] * dis + b1.w);
    float4* orow = (float4*)(out + (size_t)node * C + lane * 8);
    orow[0] = o0;
    orow[1] = o1;
}

// ---------------------------------------------------------------------------
extern "C" void kernel_launch(void* const* d_in, const int* in_sizes, int n_in,
                              void* d_out, int out_size) {
    const float* X      = (const float*)d_in[0];
    const float* W      = (const float*)d_in[1];
    const float* b      = (const float*)d_in[2];
    const int*   assign = (const int*)d_in[3];
    const int*   ei     = (const int*)d_in[4];

    int n_nodes = in_sizes[0] / C;
    int n_edges = in_sizes[4] / 2;
    const int* src = ei;
    const int* dst = ei + n_edges;
    float* out = (float*)d_out;

    cudaFuncSetAttribute(gemm_tc_kernel,
                         cudaFuncAttributeMaxDynamicSharedMemorySize, SMEM_TOTAL);

    init_wconv_kernel<<<NB_INIT + 64, 256>>>(W, n_nodes);
    edge_build_kernel<<<(n_edges + 255) / 256, 256>>>(src, dst, assign, n_edges);

    dim3 ggrid((n_nodes + BM - 1) / BM, C / BN);
    gemm_tc_kernel<<<ggrid, 256, SMEM_TOTAL>>>(X, n_nodes);

    int gth = n_nodes * 32;   // 1 warp per node
    gather_kernel<<<(gth + 255) / 256, 256>>>(X, b, assign, out, n_nodes);
}

// round 14
// speedup vs baseline: 2.9656x; 1.0586x over previous
#include <cuda_runtime.h>
#include <cuda_fp16.h>
#include <cstdint>

#define C 256            // IN_C == OUT_C == 256
#define MAX_NODES 50048
#define MAX_CLUSTERS 128
#define CAP 64           // max in-degree bucket (Poisson(5.4) -> max ~25)

// ---- GEMM tiling (fp16 m16n8k16) ----
#define BM 128           // CTA tile M (nodes)
#define BN 128           // CTA tile N (out channels)
#define BKH 64           // K halves per stage (64*2B = 128B rows)
#define NSTAGE (C / BKH) // 4
#define ROW_BYTES 144    // padded row: 9 x 16B (odd) -> conflict-free ldmatrix
#define A_BYTES (BM * ROW_BYTES)             // 18432
#define B_BYTES (BN * ROW_BYTES)             // 18432 (B stored n-major)
#define STAGE_BYTES (A_BYTES + B_BYTES)      // 36864
#define SMEM_TOTAL (2 * STAGE_BYTES)         // 73728

// Scratch (allocation-free rule: __device__ globals)
__device__ __half g_xWsh[(size_t)MAX_NODES * C]; // xW * rsqrt(deg), fp16
__device__ __half g_WhT[C * C];                  // W^T in fp16: [oc][ic]
__device__ int    g_cnt[MAX_NODES];              // intra in-degree
__device__ int    g_adj[(size_t)MAX_NODES * CAP];// per-dst src buckets
__device__ int    g_cedge[MAX_CLUSTERS];

// ---------------------------------------------------------------------------
// helpers
// ---------------------------------------------------------------------------
__device__ __forceinline__ uint32_t smem_u32(const void* p) {
    uint32_t a;
    asm("{ .reg .u64 t; cvta.to.shared.u64 t, %1; cvt.u32.u64 %0, t; }"
        : "=r"(a) : "l"(p));
    return a;
}
__device__ __forceinline__ void cp_async16(uint32_t dst, const void* src) {
    asm volatile("cp.async.cg.shared.global [%0], [%1], 16;"
                 :: "r"(dst), "l"(src) : "memory");
}
#define CP_COMMIT() asm volatile("cp.async.commit_group;" ::: "memory")
#define CP_WAIT(n)  asm volatile("cp.async.wait_group %0;" :: "n"(n) : "memory")

__device__ __forceinline__ void ldsm_x4(uint32_t& r0, uint32_t& r1,
                                        uint32_t& r2, uint32_t& r3, uint32_t addr) {
    asm volatile("ldmatrix.sync.aligned.m8n8.x4.shared.b16 {%0,%1,%2,%3}, [%4];"
                 : "=r"(r0), "=r"(r1), "=r"(r2), "=r"(r3) : "r"(addr));
}

__device__ __forceinline__ void mma_f16(float& d0, float& d1, float& d2, float& d3,
                                        uint32_t a0, uint32_t a1, uint32_t a2, uint32_t a3,
                                        uint32_t b0, uint32_t b1) {
    asm volatile(
        "mma.sync.aligned.m16n8k16.row.col.f32.f16.f16.f32 "
        "{%0,%1,%2,%3}, {%4,%5,%6,%7}, {%8,%9}, {%0,%1,%2,%3};"
        : "+f"(d0), "+f"(d1), "+f"(d2), "+f"(d3)
        : "r"(a0), "r"(a1), "r"(a2), "r"(a3), "r"(b0), "r"(b1));
}

__device__ __forceinline__ uint4 pack8h(float4 v0, float4 v1) {
    __half2 h[4];
    h[0] = __floats2half2_rn(v0.x, v0.y);
    h[1] = __floats2half2_rn(v0.z, v0.w);
    h[2] = __floats2half2_rn(v1.x, v1.y);
    h[3] = __floats2half2_rn(v1.z, v1.w);
    return *(uint4*)h;
}

// accumulate 4 half2 (a uint4) into 8 fp32 accumulators
__device__ __forceinline__ void acc8(float* a, uint4 v) {
    float2 f0 = __half22float2(*(__half2*)&v.x);
    float2 f1 = __half22float2(*(__half2*)&v.y);
    float2 f2 = __half22float2(*(__half2*)&v.z);
    float2 f3 = __half22float2(*(__half2*)&v.w);
    a[0] += f0.x; a[1] += f0.y; a[2] += f1.x; a[3] += f1.y;
    a[4] += f2.x; a[5] += f2.y; a[6] += f3.x; a[7] += f3.y;
}

// pairwise fp16 pre-add of two rows, then accumulate into fp32
__device__ __forceinline__ void acc8_pair(float* a, uint4 p, uint4 q) {
    __half2 s0 = __hadd2(*(__half2*)&p.x, *(__half2*)&q.x);
    __half2 s1 = __hadd2(*(__half2*)&p.y, *(__half2*)&q.y);
    __half2 s2 = __hadd2(*(__half2*)&p.z, *(__half2*)&q.z);
    __half2 s3 = __hadd2(*(__half2*)&p.w, *(__half2*)&q.w);
    float2 f0 = __half22float2(s0);
    float2 f1 = __half22float2(s1);
    float2 f2 = __half22float2(s2);
    float2 f3 = __half22float2(s3);
    a[0] += f0.x; a[1] += f0.y; a[2] += f1.x; a[3] += f1.y;
    a[4] += f2.x; a[5] += f2.y; a[6] += f3.x; a[7] += f3.y;
}

// ---------------------------------------------------------------------------
// Kernel 1: init counts + cluster flags  AND  W -> fp16 transposed.
// ---------------------------------------------------------------------------
#define NB_INIT 196
__global__ void init_wconv_kernel(const float* __restrict__ W, int n_nodes) {
    __shared__ float t[32][33];
    int blk = blockIdx.x;
    if (blk < NB_INIT) {
        int i = blk * 256 + threadIdx.x;
        if (i < n_nodes) g_cnt[i] = 0;
        if (i < MAX_CLUSTERS) g_cedge[i] = 0;
        return;
    }
    int wb = blk - NB_INIT;            // 0..63 -> 8x8 tiles of 32x32
    int bx = (wb & 7) * 32;            // oc tile
    int by = (wb >> 3) * 32;           // ic tile
    int tx = threadIdx.x & 31;
    int ty = threadIdx.x >> 5;         // 0..7
    for (int j = ty; j < 32; j += 8)
        t[j][tx] = W[(size_t)(by + j) * C + bx + tx];
    __syncthreads();
    for (int j = ty; j < 32; j += 8)
        g_WhT[(size_t)(bx + j) * C + by + tx] = __float2half_rn(t[tx][j]);
}

// ---------------------------------------------------------------------------
// Kernel 2: build per-dst adjacency buckets for intra-cluster edges.
// ---------------------------------------------------------------------------
__global__ void edge_build_kernel(const int* __restrict__ src,
                                  const int* __restrict__ dst,
                                  const int* __restrict__ assign,
                                  int n_edges) {
    int e = blockIdx.x * blockDim.x + threadIdx.x;
    if (e >= n_edges) return;
    int s = src[e], d = dst[e];
    int a = assign[s];
    if (a == assign[d]) {
        int pos = atomicAdd(&g_cnt[d], 1);
        if (pos < CAP) g_adj[(size_t)d * CAP + pos] = s;
        g_cedge[a] = 1;
    }
}

// ---------------------------------------------------------------------------
// Kernel 3: fp16 mma.sync GEMM. g_xWsh[row] = half((X@W)[row] * rsqrt(deg)).
// Fused fp32->fp16 A path; single __syncthreads per stage; unrolled stages.
// ---------------------------------------------------------------------------
__global__ __launch_bounds__(256, 2) void gemm_tc_kernel(
    const float* __restrict__ X, int n_nodes) {
    extern __shared__ char smem[];

    const int tid = threadIdx.x;
    const int wid = tid >> 5;
    const int lane = tid & 31;
    const int g = lane >> 2;
    const int t = lane & 3;
    const int wm = wid >> 2;
    const int wn = wid & 3;

    const int mbase = blockIdx.x * BM;
    const int nbase = blockIdx.y * BN;

    const uint32_t sbase = smem_u32(smem);

    const int a_row = lane & 15;
    const int a_byte = (lane >> 4) * 16;
    const int b_row = (lane & 7) + ((lane >> 4) * 8);
    const int b_byte = ((lane >> 3) & 1) * 16;

    const int am[4]  = { (tid + 0) >> 3, (tid + 256) >> 3, (tid + 512) >> 3, (tid + 768) >> 3 };
    const int aseg = tid & 7;

    float acc[4][4][4];
    #pragma unroll
    for (int i = 0; i < 4; i++)
        #pragma unroll
        for (int j = 0; j < 4; j++)
            #pragma unroll
            for (int k = 0; k < 4; k++) acc[i][j][k] = 0.f;

    auto ldg_a2 = [&](int ks, int c, float4& v0, float4& v1) {
        int node = mbase + am[c];
        if (node < n_nodes) {
            const float* src = X + (size_t)node * C + ks * BKH + aseg * 8;
            v0 = *(const float4*)src;
            v1 = *(const float4*)(src + 4);
        } else {
            v0 = make_float4(0.f, 0.f, 0.f, 0.f);
            v1 = v0;
        }
    };
    auto sts_a = [&](int buf, int c, float4 v0, float4 v1) {
        uint32_t off = (uint32_t)(buf * STAGE_BYTES + am[c] * ROW_BYTES + aseg * 16);
        *(uint4*)(smem + off) = pack8h(v0, v1);
    };
    auto cp_b = [&](int ks, int buf) {
        const uint32_t sB = sbase + buf * STAGE_BYTES + A_BYTES;
        #pragma unroll
        for (int p = 0; p < 4; p++) {
            int i = tid + p * 256;
            int n = i >> 3, seg = i & 7;
            const __half* src = g_WhT + (size_t)(nbase + n) * C + ks * BKH + seg * 8;
            cp_async16(sB + (uint32_t)(n * ROW_BYTES + seg * 16), src);
        }
    };
    auto compute_half = [&](uint32_t sA, uint32_t sB, int kk0) {
        #pragma unroll
        for (int kk = kk0; kk < kk0 + 32; kk += 16) {
            uint32_t af[4][4], bf[2][4];
            #pragma unroll
            for (int mi = 0; mi < 4; mi++) {
                int r = wm * 64 + mi * 16 + a_row;
                ldsm_x4(af[mi][0], af[mi][1], af[mi][2], af[mi][3],
                        sA + (uint32_t)(r * ROW_BYTES + kk * 2 + a_byte));
            }
            #pragma unroll
            for (int ni2 = 0; ni2 < 2; ni2++) {
                int n = wn * 32 + ni2 * 16 + b_row;
                ldsm_x4(bf[ni2][0], bf[ni2][1], bf[ni2][2], bf[ni2][3],
                        sB + (uint32_t)(n * ROW_BYTES + kk * 2 + b_byte));
            }
            #pragma unroll
            for (int mi = 0; mi < 4; mi++)
                #pragma unroll
                for (int ni = 0; ni < 4; ni++)
                    mma_f16(acc[mi][ni][0], acc[mi][ni][1], acc[mi][ni][2], acc[mi][ni][3],
                            af[mi][0], af[mi][1], af[mi][2], af[mi][3],
                            bf[ni >> 1][(ni & 1) * 2], bf[ni >> 1][(ni & 1) * 2 + 1]);
        }
    };

    // prologue: stage 0 (A via LDG+cvt+STS, B via cp.async)
    {
        float4 v[8];
        ldg_a2(0, 0, v[0], v[1]); ldg_a2(0, 1, v[2], v[3]);
        ldg_a2(0, 2, v[4], v[5]); ldg_a2(0, 3, v[6], v[7]);
        sts_a(0, 0, v[0], v[1]); sts_a(0, 1, v[2], v[3]);
        sts_a(0, 2, v[4], v[5]); sts_a(0, 3, v[6], v[7]);
        cp_b(0, 0);
        CP_COMMIT();
    }

    #pragma unroll
    for (int ks = 0; ks < NSTAGE; ks++) {
        const int buf = ks & 1;
        const int nbuf = buf ^ 1;
        const bool has_next = (ks < NSTAGE - 1);

        float4 pv[4];
        if (has_next) {            // prefetch A chunks 0,1 (regs) before the wait
            ldg_a2(ks + 1, 0, pv[0], pv[1]);
            ldg_a2(ks + 1, 1, pv[2], pv[3]);
        }

        CP_WAIT(0);                // current stage's B is the only pending group
        __syncthreads();           // single barrier: buf ready AND nbuf free

        if (has_next) {            // next stage's B in flight during compute
            cp_b(ks + 1, nbuf);
            CP_COMMIT();
        }

        const uint32_t sA = sbase + buf * STAGE_BYTES;
        const uint32_t sB = sA + A_BYTES;

        compute_half(sA, sB, 0);

        if (has_next) {
            sts_a(nbuf, 0, pv[0], pv[1]);
            sts_a(nbuf, 1, pv[2], pv[3]);
            ldg_a2(ks + 1, 2, pv[0], pv[1]);
            ldg_a2(ks + 1, 3, pv[2], pv[3]);
        }

        compute_half(sA, sB, 32);

        if (has_next) {
            sts_a(nbuf, 2, pv[0], pv[1]);
            sts_a(nbuf, 3, pv[2], pv[3]);
        }
    }

    // epilogue: g_xWsh[row] = half(raw * rsqrt(1 + cnt[row]))
    #pragma unroll
    for (int mi = 0; mi < 4; mi++) {
        int r0 = mbase + wm * 64 + mi * 16 + g;
        int r1 = r0 + 8;
        float dis0 = (r0 < n_nodes) ? rsqrtf(1.0f + (float)g_cnt[r0]) : 0.f;
        float dis1 = (r1 < n_nodes) ? rsqrtf(1.0f + (float)g_cnt[r1]) : 0.f;
        #pragma unroll
        for (int ni = 0; ni < 4; ni++) {
            int col = nbase + wn * 32 + ni * 8 + t * 2;
            if (r0 < n_nodes) {
                __half2 h = __floats2half2_rn(acc[mi][ni][0] * dis0, acc[mi][ni][1] * dis0);
                *(__half2*)(g_xWsh + (size_t)r0 * C + col) = h;
            }
            if (r1 < n_nodes) {
                __half2 h = __floats2half2_rn(acc[mi][ni][2] * dis1, acc[mi][ni][3] * dis1);
                *(__half2*)(g_xWsh + (size_t)r1 * C + col) = h;
            }
        }
    }
}

// ---------------------------------------------------------------------------
// Kernel 4: atomic-free gather over fp16 xWs. One warp per dst node.
// Pairwise fp16 pre-add (HADD2) halves the convert/FADD stream.
// out[d] = dis[d] * (xWs[d] + sum_{src in adj[d]} xWs[src]) + b
// ---------------------------------------------------------------------------
__global__ __launch_bounds__(256) void gather_kernel(
    const float* __restrict__ X, const float* __restrict__ b,
    const int* __restrict__ assign, float* __restrict__ out, int n_nodes) {
    int node = (blockIdx.x * blockDim.x + threadIdx.x) >> 5;
    int lane = threadIdx.x & 31;
    if (node >= n_nodes) return;

    if (g_cedge[assign[node]] == 0) {
        const float4* xrow = (const float4*)(X + (size_t)node * C);
        float4* orow = (float4*)(out + (size_t)node * C);
        orow[lane] = xrow[lane];
        orow[lane + 32] = xrow[lane + 32];
        return;
    }

    int cnt = g_cnt[node];
    if (cnt > CAP) cnt = CAP;
    float dis = rsqrtf(1.0f + (float)cnt);

    const uint4* xw = (const uint4*)g_xWsh;      // 16B = 8 halves per entry
    float a[8] = {0.f, 0.f, 0.f, 0.f, 0.f, 0.f, 0.f, 0.f};
    acc8(a, xw[(size_t)node * 32 + lane]);       // self term

    const int* adj = g_adj + (size_t)node * CAP;
    int e = 0;
    for (; e + 4 <= cnt; e += 4) {
        int s0 = adj[e], s1 = adj[e + 1], s2 = adj[e + 2], s3 = adj[e + 3];
        uint4 v0 = xw[(size_t)s0 * 32 + lane];
        uint4 v1 = xw[(size_t)s1 * 32 + lane];
        uint4 v2 = xw[(size_t)s2 * 32 + lane];
        uint4 v3 = xw[(size_t)s3 * 32 + lane];
        acc8_pair(a, v0, v1);
        acc8_pair(a, v2, v3);
    }
    if (e + 2 <= cnt) {
        uint4 v0 = xw[(size_t)adj[e] * 32 + lane];
        uint4 v1 = xw[(size_t)adj[e + 1] * 32 + lane];
        acc8_pair(a, v0, v1);
        e += 2;
    }
    if (e < cnt)
        acc8(a, xw[(size_t)adj[e] * 32 + lane]);

    const float4* brow = (const float4*)b;       // lane owns floats [lane*8, lane*8+8)
    float4 b0 = brow[lane * 2], b1 = brow[lane * 2 + 1];
    float4 o0 = make_float4(a[0] * dis + b0.x, a[1] * dis + b0.y,
                            a[2] * dis + b0.z, a[3] * dis + b0.w);
    float4 o1 = make_float4(a[4] * dis + b1.x, a[5] * dis + b1.y,
                            a[6] * dis + b1.z, a[7] * dis + b1.w);
    float4* orow = (float4*)(out + (size_t)node * C + lane * 8);
    orow[0] = o0;
    orow[1] = o1;
}

// ---------------------------------------------------------------------------
extern "C" void kernel_launch(void* const* d_in, const int* in_sizes, int n_in,
                              void* d_out, int out_size) {
    const float* X      = (const float*)d_in[0];
    const float* W      = (const float*)d_in[1];
    const float* b      = (const float*)d_in[2];
    const int*   assign = (const int*)d_in[3];
    const int*   ei     = (const int*)d_in[4];

    int n_nodes = in_sizes[0] / C;
    int n_edges = in_sizes[4] / 2;
    const int* src = ei;
    const int* dst = ei + n_edges;
    float* out = (float*)d_out;

    cudaFuncSetAttribute(gemm_tc_kernel,
                         cudaFuncAttributeMaxDynamicSharedMemorySize, SMEM_TOTAL);

    init_wconv_kernel<<<NB_INIT + 64, 256>>>(W, n_nodes);
    edge_build_kernel<<<(n_edges + 255) / 256, 256>>>(src, dst, assign, n_edges);

    dim3 ggrid((n_nodes + BM - 1) / BM, C / BN);
    gemm_tc_kernel<<<ggrid, 256, SMEM_TOTAL>>>(X, n_nodes);

    int gth = n_nodes * 32;   // 1 warp per node
    gather_kernel<<<(gth + 255) / 256, 256>>>(X, b, assign, out, n_nodes);
}